// round 1
// baseline (speedup 1.0000x reference)
#include <cuda_runtime.h>
#include <math.h>

#define Bz 2
#define Sq 1024
#define Dm 4096
#define Hh 32
#define HDim 128

// Scratch (device globals: no allocation allowed in kernel_launch)
__device__ float g_q[Bz * Sq * Dm];
__device__ float g_k[Bz * Sq * Dm];
__device__ float g_v[Bz * Sq * Dm];
__device__ float g_attn[Bz * Sq * Dm];

// ---------------------------------------------------------------------------
// GEMM: C[M,N] = A[M,K] * W[N,K]^T   (both row-major, K contiguous)
// 128x128 block tile, K-tile 16, 256 threads, 8x8 per-thread tile.
// ---------------------------------------------------------------------------
__global__ __launch_bounds__(256) void gemm_nt(const float* __restrict__ A,
                                               const float* __restrict__ W,
                                               float* __restrict__ C,
                                               int M, int N, int K) {
    __shared__ float As[16 * 132];  // [k][m], padded
    __shared__ float Bs[16 * 132];  // [k][n], padded

    const int bm = blockIdx.y * 128;
    const int bn = blockIdx.x * 128;
    const int tid = threadIdx.x;
    const int ty = tid >> 4;   // 0..15
    const int tx = tid & 15;   // 0..15

    float acc[8][8];
#pragma unroll
    for (int i = 0; i < 8; i++)
#pragma unroll
        for (int j = 0; j < 8; j++) acc[i][j] = 0.0f;

    for (int k0 = 0; k0 < K; k0 += 16) {
#pragma unroll
        for (int it = 0; it < 2; it++) {
            int f = tid + it * 256;      // 0..511 float4 slots
            int row = f >> 2;            // 0..127
            int c4 = (f & 3) << 2;       // 0,4,8,12
            float4 va = *(const float4*)(A + (size_t)(bm + row) * K + k0 + c4);
            As[(c4 + 0) * 132 + row] = va.x;
            As[(c4 + 1) * 132 + row] = va.y;
            As[(c4 + 2) * 132 + row] = va.z;
            As[(c4 + 3) * 132 + row] = va.w;
            float4 vb = *(const float4*)(W + (size_t)(bn + row) * K + k0 + c4);
            Bs[(c4 + 0) * 132 + row] = vb.x;
            Bs[(c4 + 1) * 132 + row] = vb.y;
            Bs[(c4 + 2) * 132 + row] = vb.z;
            Bs[(c4 + 3) * 132 + row] = vb.w;
        }
        __syncthreads();

#pragma unroll
        for (int kk = 0; kk < 16; kk++) {
            float4 a0 = *(float4*)&As[kk * 132 + ty * 8];
            float4 a1 = *(float4*)&As[kk * 132 + ty * 8 + 4];
            float4 b0 = *(float4*)&Bs[kk * 132 + tx * 8];
            float4 b1 = *(float4*)&Bs[kk * 132 + tx * 8 + 4];
            float a[8] = {a0.x, a0.y, a0.z, a0.w, a1.x, a1.y, a1.z, a1.w};
            float b[8] = {b0.x, b0.y, b0.z, b0.w, b1.x, b1.y, b1.z, b1.w};
#pragma unroll
            for (int i = 0; i < 8; i++)
#pragma unroll
                for (int j = 0; j < 8; j++) acc[i][j] = fmaf(a[i], b[j], acc[i][j]);
        }
        __syncthreads();
    }

#pragma unroll
    for (int i = 0; i < 8; i++) {
        float* crow = C + (size_t)(bm + ty * 8 + i) * N + bn + tx * 8;
        float4 o0 = make_float4(acc[i][0], acc[i][1], acc[i][2], acc[i][3]);
        float4 o1 = make_float4(acc[i][4], acc[i][5], acc[i][6], acc[i][7]);
        *(float4*)(crow) = o0;
        *(float4*)(crow + 4) = o1;
    }
}

// ---------------------------------------------------------------------------
// RoPE (interleaved pairs) applied in-place to Q and K.
// One thread per (b,s,h,pair).  Total = 2*1024*32*64 = 2^22 threads.
// ---------------------------------------------------------------------------
__global__ __launch_bounds__(256) void rope_kernel(float* __restrict__ Q,
                                                   float* __restrict__ K,
                                                   const float* __restrict__ fcos,
                                                   const float* __restrict__ fsin) {
    int idx = blockIdx.x * blockDim.x + threadIdx.x;
    if (idx >= Bz * Sq * Hh * (HDim / 2)) return;
    int p = idx & 63;
    int h = (idx >> 6) & 31;
    int s = (idx >> 11) & 1023;
    int b = idx >> 21;
    size_t base = ((size_t)(b * Sq + s)) * Dm + h * HDim + (p << 1);
    float c = fcos[s * 64 + p];
    float sn = fsin[s * 64 + p];
    float2 q = *(float2*)(Q + base);
    *(float2*)(Q + base) = make_float2(q.x * c - q.y * sn, q.x * sn + q.y * c);
    float2 k = *(float2*)(K + base);
    *(float2*)(K + base) = make_float2(k.x * c - k.y * sn, k.x * sn + k.y * c);
}

// ---------------------------------------------------------------------------
// Flash attention (fp32, causal). One CTA = (b,h, 64 q-rows). 256 threads.
// smem: Qt[128][68] (k-transposed), Kt[128][68], Vs[64][132], Ps[64][68]
// thread (ty,tx): computes S[qi=ty*4+i][kj=tx*4+j]; owns O dims tx*8..tx*8+7.
// ---------------------------------------------------------------------------
#define FLASH_SMEM_FLOATS (128 * 68 + 128 * 68 + 64 * 132 + 64 * 68)

__global__ __launch_bounds__(256) void flash_kernel(const float* __restrict__ Q,
                                                    const float* __restrict__ K,
                                                    const float* __restrict__ V,
                                                    float* __restrict__ O) {
    extern __shared__ float sm[];
    float* Qt = sm;                 // [kk][qi] 128x68
    float* Kt = Qt + 128 * 68;      // [kk][kj] 128x68
    float* Vs = Kt + 128 * 68;      // [kj][d]  64x132
    float* Ps = Vs + 64 * 132;      // [qi][kj] 64x68

    const int bh = blockIdx.y;
    const int b = bh >> 5;
    const int h = bh & 31;
    const int q0 = blockIdx.x * 64;

    const float* Qh = Q + ((size_t)b * Sq) * Dm + h * HDim;
    const float* Kh = K + ((size_t)b * Sq) * Dm + h * HDim;
    const float* Vh = V + ((size_t)b * Sq) * Dm + h * HDim;
    float* Oh = O + ((size_t)b * Sq) * Dm + h * HDim;

    const int tid = threadIdx.x;
    const int ty = tid >> 4;
    const int tx = tid & 15;
    const float scale = 0.08838834764831844f;  // 1/sqrt(128)

    // Load Q tile, transposed: Qt[kk][qi]
    for (int idx = tid; idx < 64 * 32; idx += 256) {
        int qi = idx >> 5;
        int c4 = (idx & 31) << 2;
        float4 v = *(const float4*)(Qh + (size_t)(q0 + qi) * Dm + c4);
        Qt[(c4 + 0) * 68 + qi] = v.x;
        Qt[(c4 + 1) * 68 + qi] = v.y;
        Qt[(c4 + 2) * 68 + qi] = v.z;
        Qt[(c4 + 3) * 68 + qi] = v.w;
    }

    float m_i[4], l_i[4], acc[4][8];
#pragma unroll
    for (int i = 0; i < 4; i++) {
        m_i[i] = -1e30f;
        l_i[i] = 0.0f;
#pragma unroll
        for (int d = 0; d < 8; d++) acc[i][d] = 0.0f;
    }

    for (int kb = 0; kb <= (int)blockIdx.x; kb++) {
        const int kbase = kb * 64;
        // Load K tile (transposed) and V tile (straight)
        for (int idx = tid; idx < 64 * 32; idx += 256) {
            int kj = idx >> 5;
            int c4 = (idx & 31) << 2;
            float4 vk = *(const float4*)(Kh + (size_t)(kbase + kj) * Dm + c4);
            Kt[(c4 + 0) * 68 + kj] = vk.x;
            Kt[(c4 + 1) * 68 + kj] = vk.y;
            Kt[(c4 + 2) * 68 + kj] = vk.z;
            Kt[(c4 + 3) * 68 + kj] = vk.w;
            float4 vv = *(const float4*)(Vh + (size_t)(kbase + kj) * Dm + c4);
            *(float4*)&Vs[kj * 132 + c4] = vv;
        }
        __syncthreads();

        // S tile: s[i][j] = q(ty*4+i) . k(tx*4+j)
        float s[4][4];
#pragma unroll
        for (int i = 0; i < 4; i++)
#pragma unroll
            for (int j = 0; j < 4; j++) s[i][j] = 0.0f;

        for (int kk = 0; kk < 128; kk++) {
            float4 a = *(float4*)&Qt[kk * 68 + ty * 4];
            float4 bb = *(float4*)&Kt[kk * 68 + tx * 4];
            float av[4] = {a.x, a.y, a.z, a.w};
            float bv[4] = {bb.x, bb.y, bb.z, bb.w};
#pragma unroll
            for (int i = 0; i < 4; i++)
#pragma unroll
                for (int j = 0; j < 4; j++) s[i][j] = fmaf(av[i], bv[j], s[i][j]);
        }

        const bool diag = (kb == (int)blockIdx.x);
#pragma unroll
        for (int i = 0; i < 4; i++) {
            const int qi_g = q0 + ty * 4 + i;
#pragma unroll
            for (int j = 0; j < 4; j++) {
                float sv = s[i][j] * scale;
                if (diag && (kbase + tx * 4 + j) > qi_g) sv = -1e30f;
                s[i][j] = sv;
            }
            // row max across 4 local + 16 tx threads (half-warp shfl)
            float mx = fmaxf(fmaxf(s[i][0], s[i][1]), fmaxf(s[i][2], s[i][3]));
            mx = fmaxf(mx, __shfl_xor_sync(0xffffffffu, mx, 8));
            mx = fmaxf(mx, __shfl_xor_sync(0xffffffffu, mx, 4));
            mx = fmaxf(mx, __shfl_xor_sync(0xffffffffu, mx, 2));
            mx = fmaxf(mx, __shfl_xor_sync(0xffffffffu, mx, 1));
            float mnew = fmaxf(m_i[i], mx);
            float p0 = __expf(s[i][0] - mnew);
            float p1 = __expf(s[i][1] - mnew);
            float p2 = __expf(s[i][2] - mnew);
            float p3 = __expf(s[i][3] - mnew);
            float rs = p0 + p1 + p2 + p3;
            rs += __shfl_xor_sync(0xffffffffu, rs, 8);
            rs += __shfl_xor_sync(0xffffffffu, rs, 4);
            rs += __shfl_xor_sync(0xffffffffu, rs, 2);
            rs += __shfl_xor_sync(0xffffffffu, rs, 1);
            float alpha = __expf(m_i[i] - mnew);
            l_i[i] = l_i[i] * alpha + rs;
            m_i[i] = mnew;
#pragma unroll
            for (int d = 0; d < 8; d++) acc[i][d] *= alpha;
            *(float4*)&Ps[(ty * 4 + i) * 68 + tx * 4] = make_float4(p0, p1, p2, p3);
        }
        __syncthreads();

        // O += P * V
        for (int j = 0; j < 64; j++) {
            float4 v0 = *(float4*)&Vs[j * 132 + tx * 8];
            float4 v1 = *(float4*)&Vs[j * 132 + tx * 8 + 4];
#pragma unroll
            for (int i = 0; i < 4; i++) {
                float pv = Ps[(ty * 4 + i) * 68 + j];
                acc[i][0] = fmaf(pv, v0.x, acc[i][0]);
                acc[i][1] = fmaf(pv, v0.y, acc[i][1]);
                acc[i][2] = fmaf(pv, v0.z, acc[i][2]);
                acc[i][3] = fmaf(pv, v0.w, acc[i][3]);
                acc[i][4] = fmaf(pv, v1.x, acc[i][4]);
                acc[i][5] = fmaf(pv, v1.y, acc[i][5]);
                acc[i][6] = fmaf(pv, v1.z, acc[i][6]);
                acc[i][7] = fmaf(pv, v1.w, acc[i][7]);
            }
        }
        __syncthreads();
    }

#pragma unroll
    for (int i = 0; i < 4; i++) {
        float inv = 1.0f / l_i[i];
        float* orow = Oh + (size_t)(q0 + ty * 4 + i) * Dm + tx * 8;
        *(float4*)(orow) =
            make_float4(acc[i][0] * inv, acc[i][1] * inv, acc[i][2] * inv, acc[i][3] * inv);
        *(float4*)(orow + 4) =
            make_float4(acc[i][4] * inv, acc[i][5] * inv, acc[i][6] * inv, acc[i][7] * inv);
    }
}

// ---------------------------------------------------------------------------
// Launch: QKV proj -> RoPE -> flash attention -> output proj
// Inputs: 0=x 1=freqs_cos 2=freqs_sin 3=mask 4=cache_k 5=cache_v
//         6=wq 7=wk 8=wv 9=wo 10=start_pos (always 0)
// ---------------------------------------------------------------------------
extern "C" void kernel_launch(void* const* d_in, const int* in_sizes, int n_in,
                              void* d_out, int out_size) {
    const float* x = (const float*)d_in[0];
    const float* fc = (const float*)d_in[1];
    const float* fs = (const float*)d_in[2];
    const float* wq = (const float*)d_in[6];
    const float* wk = (const float*)d_in[7];
    const float* wv = (const float*)d_in[8];
    const float* wo = (const float*)d_in[9];
    float* out = (float*)d_out;

    float *qp, *kp, *vp, *ap;
    cudaGetSymbolAddress((void**)&qp, g_q);
    cudaGetSymbolAddress((void**)&kp, g_k);
    cudaGetSymbolAddress((void**)&vp, g_v);
    cudaGetSymbolAddress((void**)&ap, g_attn);

    const int M = Bz * Sq;  // 2048
    dim3 gg(Dm / 128, M / 128);  // (32,16)

    gemm_nt<<<gg, 256>>>(x, wq, qp, M, Dm, Dm);
    gemm_nt<<<gg, 256>>>(x, wk, kp, M, Dm, Dm);
    gemm_nt<<<gg, 256>>>(x, wv, vp, M, Dm, Dm);

    int rope_threads = Bz * Sq * Hh * (HDim / 2);
    rope_kernel<<<rope_threads / 256, 256>>>(qp, kp, fc, fs);

    int smem_bytes = FLASH_SMEM_FLOATS * 4;
    cudaFuncSetAttribute(flash_kernel, cudaFuncAttributeMaxDynamicSharedMemorySize,
                         smem_bytes);
    dim3 fg(Sq / 64, Bz * Hh);  // (16, 64)
    flash_kernel<<<fg, 256, smem_bytes>>>(qp, kp, vp, ap);

    gemm_nt<<<gg, 256>>>(ap, wo, out, M, Dm, Dm);
}

// round 4
// speedup vs baseline: 2.3471x; 2.3471x over previous
#include <cuda_runtime.h>
#include <math.h>
#include <stdint.h>

#define Bz 2
#define Sq 1024
#define Dm 4096
#define Hh 32
#define HDim 128

// Scratch (device globals: no allocation allowed in kernel_launch)
__device__ float g_q[Bz * Sq * Dm];
__device__ float g_k[Bz * Sq * Dm];
__device__ float g_v[Bz * Sq * Dm];
__device__ float g_attn[Bz * Sq * Dm];

// ---------------------------------------------------------------------------
// TF32 tensor-core GEMM: C[M,N] = A[M,K] * W[N,K]^T  (row-major, K contiguous)
// CTA tile 128x128, K-tile 32, 8 warps (warp tile 64m x 32n), mma.m16n8k8.tf32
// Smem rows padded to 36 -> fragment LDS bank pattern (4g+t)%32: conflict-free.
// ---------------------------------------------------------------------------
__device__ __forceinline__ uint32_t f2tf32(float f) {
    uint32_t u;
    asm volatile("cvt.rna.tf32.f32 %0, %1;" : "=r"(u) : "f"(f));
    return u;
}

__global__ __launch_bounds__(256) void gemm_tf32(const float* __restrict__ A,
                                                 const float* __restrict__ W,
                                                 float* __restrict__ C,
                                                 int M, int N, int K) {
    __shared__ uint32_t As[128 * 36];
    __shared__ uint32_t Bs[128 * 36];

    const int bm = blockIdx.y * 128;
    const int bn = blockIdx.x * 128;
    const int tid = threadIdx.x;
    const int wid = tid >> 5;
    const int lane = tid & 31;
    const int g = lane >> 2;   // 0..7
    const int t = lane & 3;    // 0..3
    const int warp_m = (wid & 1) * 64;   // 0 or 64
    const int warp_n = (wid >> 1) * 32;  // 0,32,64,96

    // Load assignment: 4 float4 chunks each for A and B per thread per k-tile
    const int lrow[4] = {(tid + 0) >> 3, (tid + 256) >> 3, (tid + 512) >> 3, (tid + 768) >> 3};
    const int lcol = (tid & 7) * 4;

    float c[4][4][4];
#pragma unroll
    for (int mi = 0; mi < 4; mi++)
#pragma unroll
        for (int ni = 0; ni < 4; ni++)
#pragma unroll
            for (int r = 0; r < 4; r++) c[mi][ni][r] = 0.0f;

    float4 pa[4], pb[4];
    // initial prefetch (k-tile 0)
#pragma unroll
    for (int i = 0; i < 4; i++) {
        pa[i] = *(const float4*)(A + (size_t)(bm + lrow[i]) * K + lcol);
        pb[i] = *(const float4*)(W + (size_t)(bn + lrow[i]) * K + lcol);
    }

    for (int k0 = 0; k0 < K; k0 += 32) {
        // store current prefetch (with tf32 rounding)
#pragma unroll
        for (int i = 0; i < 4; i++) {
            uint32_t* da = &As[lrow[i] * 36 + lcol];
            da[0] = f2tf32(pa[i].x); da[1] = f2tf32(pa[i].y);
            da[2] = f2tf32(pa[i].z); da[3] = f2tf32(pa[i].w);
            uint32_t* db = &Bs[lrow[i] * 36 + lcol];
            db[0] = f2tf32(pb[i].x); db[1] = f2tf32(pb[i].y);
            db[2] = f2tf32(pb[i].z); db[3] = f2tf32(pb[i].w);
        }
        __syncthreads();

        // prefetch next k-tile
        if (k0 + 32 < K) {
#pragma unroll
            for (int i = 0; i < 4; i++) {
                pa[i] = *(const float4*)(A + (size_t)(bm + lrow[i]) * K + k0 + 32 + lcol);
                pb[i] = *(const float4*)(W + (size_t)(bn + lrow[i]) * K + k0 + 32 + lcol);
            }
        }

        // compute: 4 k8 steps
#pragma unroll
        for (int kk = 0; kk < 4; kk++) {
            const int kb = kk * 8;
            uint32_t af[4][4];
#pragma unroll
            for (int mi = 0; mi < 4; mi++) {
                const int mb = warp_m + mi * 16;
                af[mi][0] = As[(mb + g) * 36 + kb + t];
                af[mi][1] = As[(mb + g + 8) * 36 + kb + t];
                af[mi][2] = As[(mb + g) * 36 + kb + t + 4];
                af[mi][3] = As[(mb + g + 8) * 36 + kb + t + 4];
            }
#pragma unroll
            for (int ni = 0; ni < 4; ni++) {
                const int nb = warp_n + ni * 8;
                uint32_t b0 = Bs[(nb + g) * 36 + kb + t];
                uint32_t b1 = Bs[(nb + g) * 36 + kb + t + 4];
#pragma unroll
                for (int mi = 0; mi < 4; mi++) {
                    asm volatile(
                        "mma.sync.aligned.m16n8k8.row.col.f32.tf32.tf32.f32 "
                        "{%0,%1,%2,%3}, {%4,%5,%6,%7}, {%8,%9}, {%0,%1,%2,%3};"
                        : "+f"(c[mi][ni][0]), "+f"(c[mi][ni][1]),
                          "+f"(c[mi][ni][2]), "+f"(c[mi][ni][3])
                        : "r"(af[mi][0]), "r"(af[mi][1]), "r"(af[mi][2]), "r"(af[mi][3]),
                          "r"(b0), "r"(b1));
                }
            }
        }
        __syncthreads();
    }

    // epilogue: c0,c1 -> (row g, cols 2t,2t+1); c2,c3 -> (row g+8)
#pragma unroll
    for (int mi = 0; mi < 4; mi++) {
        const int row = bm + warp_m + mi * 16 + g;
#pragma unroll
        for (int ni = 0; ni < 4; ni++) {
            const int col = bn + warp_n + ni * 8 + 2 * t;
            *(float2*)(C + (size_t)row * N + col) = make_float2(c[mi][ni][0], c[mi][ni][1]);
            *(float2*)(C + (size_t)(row + 8) * N + col) = make_float2(c[mi][ni][2], c[mi][ni][3]);
        }
    }
}

// ---------------------------------------------------------------------------
// RoPE (interleaved pairs) applied in-place to Q and K.
// ---------------------------------------------------------------------------
__global__ __launch_bounds__(256) void rope_kernel(float* __restrict__ Q,
                                                   float* __restrict__ K,
                                                   const float* __restrict__ fcos,
                                                   const float* __restrict__ fsin) {
    int idx = blockIdx.x * blockDim.x + threadIdx.x;
    if (idx >= Bz * Sq * Hh * (HDim / 2)) return;
    int p = idx & 63;
    int s = (idx >> 11) & 1023;
    int b = idx >> 21;
    int h = (idx >> 6) & 31;
    size_t base = ((size_t)(b * Sq + s)) * Dm + h * HDim + (p << 1);
    float c = fcos[s * 64 + p];
    float sn = fsin[s * 64 + p];
    float2 q = *(float2*)(Q + base);
    *(float2*)(Q + base) = make_float2(q.x * c - q.y * sn, q.x * sn + q.y * c);
    float2 k = *(float2*)(K + base);
    *(float2*)(K + base) = make_float2(k.x * c - k.y * sn, k.x * sn + k.y * c);
}

// ---------------------------------------------------------------------------
// Flash attention (fp32, causal). One CTA = (b,h, 64 q-rows). 256 threads.
// ---------------------------------------------------------------------------
#define FLASH_SMEM_FLOATS (128 * 68 + 128 * 68 + 64 * 132 + 64 * 68)

__global__ __launch_bounds__(256) void flash_kernel(const float* __restrict__ Q,
                                                    const float* __restrict__ K,
                                                    const float* __restrict__ V,
                                                    float* __restrict__ O) {
    extern __shared__ float sm[];
    float* Qt = sm;                 // [kk][qi] 128x68
    float* Kt = Qt + 128 * 68;      // [kk][kj] 128x68
    float* Vs = Kt + 128 * 68;      // [kj][d]  64x132
    float* Ps = Vs + 64 * 132;      // [qi][kj] 64x68

    const int bh = blockIdx.y;
    const int b = bh >> 5;
    const int h = bh & 31;
    const int q0 = blockIdx.x * 64;

    const float* Qh = Q + ((size_t)b * Sq) * Dm + h * HDim;
    const float* Kh = K + ((size_t)b * Sq) * Dm + h * HDim;
    const float* Vh = V + ((size_t)b * Sq) * Dm + h * HDim;
    float* Oh = O + ((size_t)b * Sq) * Dm + h * HDim;

    const int tid = threadIdx.x;
    const int ty = tid >> 4;
    const int tx = tid & 15;
    const float scale = 0.08838834764831844f;  // 1/sqrt(128)

    for (int idx = tid; idx < 64 * 32; idx += 256) {
        int qi = idx >> 5;
        int c4 = (idx & 31) << 2;
        float4 v = *(const float4*)(Qh + (size_t)(q0 + qi) * Dm + c4);
        Qt[(c4 + 0) * 68 + qi] = v.x;
        Qt[(c4 + 1) * 68 + qi] = v.y;
        Qt[(c4 + 2) * 68 + qi] = v.z;
        Qt[(c4 + 3) * 68 + qi] = v.w;
    }

    float m_i[4], l_i[4], acc[4][8];
#pragma unroll
    for (int i = 0; i < 4; i++) {
        m_i[i] = -1e30f;
        l_i[i] = 0.0f;
#pragma unroll
        for (int d = 0; d < 8; d++) acc[i][d] = 0.0f;
    }

    for (int kb = 0; kb <= (int)blockIdx.x; kb++) {
        const int kbase = kb * 64;
        for (int idx = tid; idx < 64 * 32; idx += 256) {
            int kj = idx >> 5;
            int c4 = (idx & 31) << 2;
            float4 vk = *(const float4*)(Kh + (size_t)(kbase + kj) * Dm + c4);
            Kt[(c4 + 0) * 68 + kj] = vk.x;
            Kt[(c4 + 1) * 68 + kj] = vk.y;
            Kt[(c4 + 2) * 68 + kj] = vk.z;
            Kt[(c4 + 3) * 68 + kj] = vk.w;
            float4 vv = *(const float4*)(Vh + (size_t)(kbase + kj) * Dm + c4);
            *(float4*)&Vs[kj * 132 + c4] = vv;
        }
        __syncthreads();

        float s[4][4];
#pragma unroll
        for (int i = 0; i < 4; i++)
#pragma unroll
            for (int j = 0; j < 4; j++) s[i][j] = 0.0f;

        for (int kk = 0; kk < 128; kk++) {
            float4 a = *(float4*)&Qt[kk * 68 + ty * 4];
            float4 bb = *(float4*)&Kt[kk * 68 + tx * 4];
            float av[4] = {a.x, a.y, a.z, a.w};
            float bv[4] = {bb.x, bb.y, bb.z, bb.w};
#pragma unroll
            for (int i = 0; i < 4; i++)
#pragma unroll
                for (int j = 0; j < 4; j++) s[i][j] = fmaf(av[i], bv[j], s[i][j]);
        }

        const bool diag = (kb == (int)blockIdx.x);
#pragma unroll
        for (int i = 0; i < 4; i++) {
            const int qi_g = q0 + ty * 4 + i;
#pragma unroll
            for (int j = 0; j < 4; j++) {
                float sv = s[i][j] * scale;
                if (diag && (kbase + tx * 4 + j) > qi_g) sv = -1e30f;
                s[i][j] = sv;
            }
            float mx = fmaxf(fmaxf(s[i][0], s[i][1]), fmaxf(s[i][2], s[i][3]));
            mx = fmaxf(mx, __shfl_xor_sync(0xffffffffu, mx, 8));
            mx = fmaxf(mx, __shfl_xor_sync(0xffffffffu, mx, 4));
            mx = fmaxf(mx, __shfl_xor_sync(0xffffffffu, mx, 2));
            mx = fmaxf(mx, __shfl_xor_sync(0xffffffffu, mx, 1));
            float mnew = fmaxf(m_i[i], mx);
            float p0 = __expf(s[i][0] - mnew);
            float p1 = __expf(s[i][1] - mnew);
            float p2 = __expf(s[i][2] - mnew);
            float p3 = __expf(s[i][3] - mnew);
            float rs = p0 + p1 + p2 + p3;
            rs += __shfl_xor_sync(0xffffffffu, rs, 8);
            rs += __shfl_xor_sync(0xffffffffu, rs, 4);
            rs += __shfl_xor_sync(0xffffffffu, rs, 2);
            rs += __shfl_xor_sync(0xffffffffu, rs, 1);
            float alpha = __expf(m_i[i] - mnew);
            l_i[i] = l_i[i] * alpha + rs;
            m_i[i] = mnew;
#pragma unroll
            for (int d = 0; d < 8; d++) acc[i][d] *= alpha;
            *(float4*)&Ps[(ty * 4 + i) * 68 + tx * 4] = make_float4(p0, p1, p2, p3);
        }
        __syncthreads();

        for (int j = 0; j < 64; j++) {
            float4 v0 = *(float4*)&Vs[j * 132 + tx * 8];
            float4 v1 = *(float4*)&Vs[j * 132 + tx * 8 + 4];
#pragma unroll
            for (int i = 0; i < 4; i++) {
                float pv = Ps[(ty * 4 + i) * 68 + j];
                acc[i][0] = fmaf(pv, v0.x, acc[i][0]);
                acc[i][1] = fmaf(pv, v0.y, acc[i][1]);
                acc[i][2] = fmaf(pv, v0.z, acc[i][2]);
                acc[i][3] = fmaf(pv, v0.w, acc[i][3]);
                acc[i][4] = fmaf(pv, v1.x, acc[i][4]);
                acc[i][5] = fmaf(pv, v1.y, acc[i][5]);
                acc[i][6] = fmaf(pv, v1.z, acc[i][6]);
                acc[i][7] = fmaf(pv, v1.w, acc[i][7]);
            }
        }
        __syncthreads();
    }

#pragma unroll
    for (int i = 0; i < 4; i++) {
        float inv = 1.0f / l_i[i];
        float* orow = Oh + (size_t)(q0 + ty * 4 + i) * Dm + tx * 8;
        *(float4*)(orow) =
            make_float4(acc[i][0] * inv, acc[i][1] * inv, acc[i][2] * inv, acc[i][3] * inv);
        *(float4*)(orow + 4) =
            make_float4(acc[i][4] * inv, acc[i][5] * inv, acc[i][6] * inv, acc[i][7] * inv);
    }
}

// ---------------------------------------------------------------------------
// Launch
// ---------------------------------------------------------------------------
extern "C" void kernel_launch(void* const* d_in, const int* in_sizes, int n_in,
                              void* d_out, int out_size) {
    const float* x = (const float*)d_in[0];
    const float* fc = (const float*)d_in[1];
    const float* fs = (const float*)d_in[2];
    const float* wq = (const float*)d_in[6];
    const float* wk = (const float*)d_in[7];
    const float* wv = (const float*)d_in[8];
    const float* wo = (const float*)d_in[9];
    float* out = (float*)d_out;

    float *qp, *kp, *vp, *ap;
    cudaGetSymbolAddress((void**)&qp, g_q);
    cudaGetSymbolAddress((void**)&kp, g_k);
    cudaGetSymbolAddress((void**)&vp, g_v);
    cudaGetSymbolAddress((void**)&ap, g_attn);

    const int M = Bz * Sq;       // 2048
    dim3 gg(Dm / 128, M / 128);  // (32,16)

    gemm_tf32<<<gg, 256>>>(x, wq, qp, M, Dm, Dm);
    gemm_tf32<<<gg, 256>>>(x, wk, kp, M, Dm, Dm);
    gemm_tf32<<<gg, 256>>>(x, wv, vp, M, Dm, Dm);

    int rope_threads = Bz * Sq * Hh * (HDim / 2);
    rope_kernel<<<rope_threads / 256, 256>>>(qp, kp, fc, fs);

    int smem_bytes = FLASH_SMEM_FLOATS * 4;
    cudaFuncSetAttribute(flash_kernel, cudaFuncAttributeMaxDynamicSharedMemorySize,
                         smem_bytes);
    dim3 fg(Sq / 64, Bz * Hh);  // (16, 64)
    flash_kernel<<<fg, 256, smem_bytes>>>(qp, kp, vp, ap);

    gemm_tf32<<<gg, 256>>>(ap, wo, out, M, Dm, Dm);
}

// round 8
// speedup vs baseline: 2.9005x; 1.2358x over previous
#include <cuda_runtime.h>
#include <math.h>
#include <stdint.h>

#define Bz 2
#define Sq 1024
#define Dm 4096
#define Hh 32
#define HDim 128

// Scratch (device globals: no allocation allowed in kernel_launch)
__device__ float g_q[Bz * Sq * Dm];
__device__ float g_k[Bz * Sq * Dm];
__device__ float g_v[Bz * Sq * Dm];
__device__ float g_attn[Bz * Sq * Dm];   // tf32-rounded flash output
__device__ float g_xr[Bz * Sq * Dm];     // tf32-rounded x
__device__ float g_wq[Dm * Dm];
__device__ float g_wk[Dm * Dm];
__device__ float g_wv[Dm * Dm];
__device__ float g_wo[Dm * Dm];

// ===========================================================================
// helpers
// ===========================================================================
__device__ __forceinline__ uint32_t smem_u32(const void* p) {
    uint32_t a;
    asm("{ .reg .u64 t; cvta.to.shared.u64 t, %1; cvt.u32.u64 %0, t; }" : "=r"(a) : "l"(p));
    return a;
}
__device__ __forceinline__ uint32_t f2tf32(float f) {
    uint32_t u;
    asm volatile("cvt.rna.tf32.f32 %0, %1;" : "=r"(u) : "f"(f));
    return u;
}
#define CP_ASYNC_CG(dst, src) \
    asm volatile("cp.async.cg.shared.global [%0], [%1], 16;" :: "r"(dst), "l"(src))
#define CP_ASYNC_COMMIT() asm volatile("cp.async.commit_group;" ::: "memory")
#define CP_ASYNC_WAIT(n) asm volatile("cp.async.wait_group %0;" :: "n"(n) : "memory")

__device__ __forceinline__ uint32_t lds32(uint32_t addr) {
    uint32_t v;
    asm volatile("ld.shared.b32 %0, [%1];" : "=r"(v) : "r"(addr));
    return v;
}

// ===========================================================================
// Prep: elementwise tf32 (rna) rounding
// ===========================================================================
__global__ __launch_bounds__(256) void round_tf32_kernel(const float4* __restrict__ src,
                                                         float4* __restrict__ dst, int n4) {
    int i = blockIdx.x * blockDim.x + threadIdx.x;
    if (i >= n4) return;
    float4 v = src[i];
    float4 o;
    o.x = __uint_as_float(f2tf32(v.x));
    o.y = __uint_as_float(f2tf32(v.y));
    o.z = __uint_as_float(f2tf32(v.z));
    o.w = __uint_as_float(f2tf32(v.w));
    dst[i] = o;
}

// ===========================================================================
// TF32 mma.sync GEMM with 3-stage cp.async pipeline.
// C[M,N] = A[M,K] * W[N,K]^T  (row-major, K contiguous; A,W pre-tf32-rounded)
// CTA 128x128, k-tile 32 (128B rows), 8 warps (64m x 32n), m16n8k8.
// Smem chunks XOR-swizzled: chunk' = chunk ^ (row & 7)  -> conflict-free.
// ===========================================================================
#define BM 128
#define BN 128
#define BK 32
#define STAGES 3
#define STAGE_BYTES ((BM + BN) * BK * 4)      // 32768
#define GEMM_SMEM (STAGES * STAGE_BYTES)      // 98304

__global__ __launch_bounds__(256, 2) void gemm_mma(const float* __restrict__ A,
                                                   const float* __restrict__ W,
                                                   float* __restrict__ C,
                                                   int M, int N, int K) {
    extern __shared__ char smem[];
    const uint32_t sbase = smem_u32(smem);
    const int tid = threadIdx.x;
    const int wid = tid >> 5;
    const int lane = tid & 31;
    const int g = lane >> 2;     // 0..7
    const int t = lane & 3;      // 0..3
    const int warp_m = (wid & 1) * 64;
    const int warp_n = (wid >> 1) * 32;
    const int bm = blockIdx.y * BM;
    const int bn = blockIdx.x * BN;
    const int niter = K / BK;    // 128

    // per-thread load map (4 A-chunks + 4 B-chunks of 16B per stage)
    const int lrow = tid >> 3;        // 0..31 (+32*i)
    const int lc = tid & 7;           // chunk 0..7

    float acc[4][4][4];
#pragma unroll
    for (int mi = 0; mi < 4; mi++)
#pragma unroll
        for (int ni = 0; ni < 4; ni++)
#pragma unroll
            for (int r = 0; r < 4; r++) acc[mi][ni][r] = 0.0f;

    // ---- issue loads for ktile kt into stage s ----
    auto issue = [&](int kt, int s) {
        if (kt < niter) {
            const uint32_t sA = sbase + s * STAGE_BYTES;
            const uint32_t sB = sA + BM * 128;
            const int k0 = kt * BK;
#pragma unroll
            for (int i = 0; i < 4; i++) {
                int row = lrow + i * 32;
                uint32_t dst = sA + row * 128 + ((lc ^ (row & 7)) << 4);
                const float* src = A + (size_t)(bm + row) * K + k0 + lc * 4;
                CP_ASYNC_CG(dst, src);
            }
#pragma unroll
            for (int i = 0; i < 4; i++) {
                int row = lrow + i * 32;
                uint32_t dst = sB + row * 128 + ((lc ^ (row & 7)) << 4);
                const float* src = W + (size_t)(bn + row) * K + k0 + lc * 4;
                CP_ASYNC_CG(dst, src);
            }
        }
        CP_ASYNC_COMMIT();
    };

    // prologue: stages 0..STAGES-2
#pragma unroll
    for (int s = 0; s < STAGES - 1; s++) issue(s, s);

    int rs = 0;
    for (int kt = 0; kt < niter; kt++) {
        CP_ASYNC_WAIT(STAGES - 2);
        __syncthreads();
        // issue future stage (safe: all threads finished reading that stage)
        issue(kt + STAGES - 1, (rs + STAGES - 1 >= STAGES) ? rs - 1 : rs + STAGES - 1);

        const uint32_t sA = sbase + rs * STAGE_BYTES;
        const uint32_t sB = sA + BM * 128;
#pragma unroll
        for (int ks = 0; ks < 4; ks++) {
            const int ch0 = ks * 2;       // kb = ks*8 -> chunk kb/4
            const int ch1 = ch0 + 1;
            const int c0 = ((ch0 ^ g) << 4) + t * 4;
            const int c1 = ((ch1 ^ g) << 4) + t * 4;
            uint32_t af[4][4];
#pragma unroll
            for (int mi = 0; mi < 4; mi++) {
                const int r0 = warp_m + mi * 16 + g;
                af[mi][0] = lds32(sA + r0 * 128 + c0);
                af[mi][1] = lds32(sA + (r0 + 8) * 128 + c0);
                af[mi][2] = lds32(sA + r0 * 128 + c1);
                af[mi][3] = lds32(sA + (r0 + 8) * 128 + c1);
            }
#pragma unroll
            for (int ni = 0; ni < 4; ni++) {
                const int rn = warp_n + ni * 8 + g;
                uint32_t b0 = lds32(sB + rn * 128 + c0);
                uint32_t b1 = lds32(sB + rn * 128 + c1);
#pragma unroll
                for (int mi = 0; mi < 4; mi++) {
                    asm volatile(
                        "mma.sync.aligned.m16n8k8.row.col.f32.tf32.tf32.f32 "
                        "{%0,%1,%2,%3}, {%4,%5,%6,%7}, {%8,%9}, {%0,%1,%2,%3};"
                        : "+f"(acc[mi][ni][0]), "+f"(acc[mi][ni][1]),
                          "+f"(acc[mi][ni][2]), "+f"(acc[mi][ni][3])
                        : "r"(af[mi][0]), "r"(af[mi][1]), "r"(af[mi][2]), "r"(af[mi][3]),
                          "r"(b0), "r"(b1));
                }
            }
        }
        if (++rs == STAGES) rs = 0;
    }

    // epilogue
#pragma unroll
    for (int mi = 0; mi < 4; mi++) {
        const int row = bm + warp_m + mi * 16 + g;
#pragma unroll
        for (int ni = 0; ni < 4; ni++) {
            const int col = bn + warp_n + ni * 8 + 2 * t;
            *(float2*)(C + (size_t)row * N + col) =
                make_float2(acc[mi][ni][0], acc[mi][ni][1]);
            *(float2*)(C + (size_t)(row + 8) * N + col) =
                make_float2(acc[mi][ni][2], acc[mi][ni][3]);
        }
    }
}

// ---------------------------------------------------------------------------
// RoPE (interleaved pairs) applied in-place to Q and K.
// ---------------------------------------------------------------------------
__global__ __launch_bounds__(256) void rope_kernel(float* __restrict__ Q,
                                                   float* __restrict__ K,
                                                   const float* __restrict__ fcos,
                                                   const float* __restrict__ fsin) {
    int idx = blockIdx.x * blockDim.x + threadIdx.x;
    if (idx >= Bz * Sq * Hh * (HDim / 2)) return;
    int p = idx & 63;
    int s = (idx >> 11) & 1023;
    int b = idx >> 21;
    int h = (idx >> 6) & 31;
    size_t base = ((size_t)(b * Sq + s)) * Dm + h * HDim + (p << 1);
    float c = fcos[s * 64 + p];
    float sn = fsin[s * 64 + p];
    float2 q = *(float2*)(Q + base);
    *(float2*)(Q + base) = make_float2(q.x * c - q.y * sn, q.x * sn + q.y * c);
    float2 k = *(float2*)(K + base);
    *(float2*)(K + base) = make_float2(k.x * c - k.y * sn, k.x * sn + k.y * c);
}

// ---------------------------------------------------------------------------
// Flash attention (fp32, causal). One CTA = (b,h, 64 q-rows). 256 threads.
// Output rounded to tf32 (rna) so the O-projection GEMM can consume raw bits.
// ---------------------------------------------------------------------------
#define FLASH_SMEM_FLOATS (128 * 68 + 128 * 68 + 64 * 132 + 64 * 68)

__global__ __launch_bounds__(256) void flash_kernel(const float* __restrict__ Q,
                                                    const float* __restrict__ K,
                                                    const float* __restrict__ V,
                                                    float* __restrict__ O) {
    extern __shared__ float sm[];
    float* Qt = sm;                 // [kk][qi] 128x68
    float* Kt = Qt + 128 * 68;      // [kk][kj] 128x68
    float* Vs = Kt + 128 * 68;      // [kj][d]  64x132
    float* Ps = Vs + 64 * 132;      // [qi][kj] 64x68

    const int bh = blockIdx.y;
    const int b = bh >> 5;
    const int h = bh & 31;
    const int q0 = blockIdx.x * 64;

    const float* Qh = Q + ((size_t)b * Sq) * Dm + h * HDim;
    const float* Kh = K + ((size_t)b * Sq) * Dm + h * HDim;
    const float* Vh = V + ((size_t)b * Sq) * Dm + h * HDim;
    float* Oh = O + ((size_t)b * Sq) * Dm + h * HDim;

    const int tid = threadIdx.x;
    const int ty = tid >> 4;
    const int tx = tid & 15;
    const float scale = 0.08838834764831844f;  // 1/sqrt(128)

    for (int idx = tid; idx < 64 * 32; idx += 256) {
        int qi = idx >> 5;
        int c4 = (idx & 31) << 2;
        float4 v = *(const float4*)(Qh + (size_t)(q0 + qi) * Dm + c4);
        Qt[(c4 + 0) * 68 + qi] = v.x;
        Qt[(c4 + 1) * 68 + qi] = v.y;
        Qt[(c4 + 2) * 68 + qi] = v.z;
        Qt[(c4 + 3) * 68 + qi] = v.w;
    }

    float m_i[4], l_i[4], acc[4][8];
#pragma unroll
    for (int i = 0; i < 4; i++) {
        m_i[i] = -1e30f;
        l_i[i] = 0.0f;
#pragma unroll
        for (int d = 0; d < 8; d++) acc[i][d] = 0.0f;
    }

    for (int kb = 0; kb <= (int)blockIdx.x; kb++) {
        const int kbase = kb * 64;
        for (int idx = tid; idx < 64 * 32; idx += 256) {
            int kj = idx >> 5;
            int c4 = (idx & 31) << 2;
            float4 vk = *(const float4*)(Kh + (size_t)(kbase + kj) * Dm + c4);
            Kt[(c4 + 0) * 68 + kj] = vk.x;
            Kt[(c4 + 1) * 68 + kj] = vk.y;
            Kt[(c4 + 2) * 68 + kj] = vk.z;
            Kt[(c4 + 3) * 68 + kj] = vk.w;
            float4 vv = *(const float4*)(Vh + (size_t)(kbase + kj) * Dm + c4);
            *(float4*)&Vs[kj * 132 + c4] = vv;
        }
        __syncthreads();

        float s[4][4];
#pragma unroll
        for (int i = 0; i < 4; i++)
#pragma unroll
            for (int j = 0; j < 4; j++) s[i][j] = 0.0f;

        for (int kk = 0; kk < 128; kk++) {
            float4 a = *(float4*)&Qt[kk * 68 + ty * 4];
            float4 bb = *(float4*)&Kt[kk * 68 + tx * 4];
            float av[4] = {a.x, a.y, a.z, a.w};
            float bv[4] = {bb.x, bb.y, bb.z, bb.w};
#pragma unroll
            for (int i = 0; i < 4; i++)
#pragma unroll
                for (int j = 0; j < 4; j++) s[i][j] = fmaf(av[i], bv[j], s[i][j]);
        }

        const bool diag = (kb == (int)blockIdx.x);
#pragma unroll
        for (int i = 0; i < 4; i++) {
            const int qi_g = q0 + ty * 4 + i;
#pragma unroll
            for (int j = 0; j < 4; j++) {
                float sv = s[i][j] * scale;
                if (diag && (kbase + tx * 4 + j) > qi_g) sv = -1e30f;
                s[i][j] = sv;
            }
            float mx = fmaxf(fmaxf(s[i][0], s[i][1]), fmaxf(s[i][2], s[i][3]));
            mx = fmaxf(mx, __shfl_xor_sync(0xffffffffu, mx, 8));
            mx = fmaxf(mx, __shfl_xor_sync(0xffffffffu, mx, 4));
            mx = fmaxf(mx, __shfl_xor_sync(0xffffffffu, mx, 2));
            mx = fmaxf(mx, __shfl_xor_sync(0xffffffffu, mx, 1));
            float mnew = fmaxf(m_i[i], mx);
            float p0 = __expf(s[i][0] - mnew);
            float p1 = __expf(s[i][1] - mnew);
            float p2 = __expf(s[i][2] - mnew);
            float p3 = __expf(s[i][3] - mnew);
            float rs = p0 + p1 + p2 + p3;
            rs += __shfl_xor_sync(0xffffffffu, rs, 8);
            rs += __shfl_xor_sync(0xffffffffu, rs, 4);
            rs += __shfl_xor_sync(0xffffffffu, rs, 2);
            rs += __shfl_xor_sync(0xffffffffu, rs, 1);
            float alpha = __expf(m_i[i] - mnew);
            l_i[i] = l_i[i] * alpha + rs;
            m_i[i] = mnew;
#pragma unroll
            for (int d = 0; d < 8; d++) acc[i][d] *= alpha;
            *(float4*)&Ps[(ty * 4 + i) * 68 + tx * 4] = make_float4(p0, p1, p2, p3);
        }
        __syncthreads();

        for (int j = 0; j < 64; j++) {
            float4 v0 = *(float4*)&Vs[j * 132 + tx * 8];
            float4 v1 = *(float4*)&Vs[j * 132 + tx * 8 + 4];
#pragma unroll
            for (int i = 0; i < 4; i++) {
                float pv = Ps[(ty * 4 + i) * 68 + j];
                acc[i][0] = fmaf(pv, v0.x, acc[i][0]);
                acc[i][1] = fmaf(pv, v0.y, acc[i][1]);
                acc[i][2] = fmaf(pv, v0.z, acc[i][2]);
                acc[i][3] = fmaf(pv, v0.w, acc[i][3]);
                acc[i][4] = fmaf(pv, v1.x, acc[i][4]);
                acc[i][5] = fmaf(pv, v1.y, acc[i][5]);
                acc[i][6] = fmaf(pv, v1.z, acc[i][6]);
                acc[i][7] = fmaf(pv, v1.w, acc[i][7]);
            }
        }
        __syncthreads();
    }

#pragma unroll
    for (int i = 0; i < 4; i++) {
        float inv = 1.0f / l_i[i];
        float* orow = Oh + (size_t)(q0 + ty * 4 + i) * Dm + tx * 8;
        float4 o0, o1;
        o0.x = __uint_as_float(f2tf32(acc[i][0] * inv));
        o0.y = __uint_as_float(f2tf32(acc[i][1] * inv));
        o0.z = __uint_as_float(f2tf32(acc[i][2] * inv));
        o0.w = __uint_as_float(f2tf32(acc[i][3] * inv));
        o1.x = __uint_as_float(f2tf32(acc[i][4] * inv));
        o1.y = __uint_as_float(f2tf32(acc[i][5] * inv));
        o1.z = __uint_as_float(f2tf32(acc[i][6] * inv));
        o1.w = __uint_as_float(f2tf32(acc[i][7] * inv));
        *(float4*)(orow) = o0;
        *(float4*)(orow + 4) = o1;
    }
}

// ---------------------------------------------------------------------------
// Launch: round inputs -> QKV proj -> RoPE -> flash -> O proj
// ---------------------------------------------------------------------------
extern "C" void kernel_launch(void* const* d_in, const int* in_sizes, int n_in,
                              void* d_out, int out_size) {
    const float* x = (const float*)d_in[0];
    const float* fc = (const float*)d_in[1];
    const float* fs = (const float*)d_in[2];
    const float* wq = (const float*)d_in[6];
    const float* wk = (const float*)d_in[7];
    const float* wv = (const float*)d_in[8];
    const float* wo = (const float*)d_in[9];
    float* out = (float*)d_out;

    float *qp, *kp, *vp, *ap, *xr, *wqr, *wkr, *wvr, *wor;
    cudaGetSymbolAddress((void**)&qp, g_q);
    cudaGetSymbolAddress((void**)&kp, g_k);
    cudaGetSymbolAddress((void**)&vp, g_v);
    cudaGetSymbolAddress((void**)&ap, g_attn);
    cudaGetSymbolAddress((void**)&xr, g_xr);
    cudaGetSymbolAddress((void**)&wqr, g_wq);
    cudaGetSymbolAddress((void**)&wkr, g_wk);
    cudaGetSymbolAddress((void**)&wvr, g_wv);
    cudaGetSymbolAddress((void**)&wor, g_wo);

    const int M = Bz * Sq;  // 2048

    // prep: tf32-round x and weights
    {
        int nx4 = (Bz * Sq * Dm) / 4;
        int nw4 = (Dm * Dm) / 4;
        round_tf32_kernel<<<(nx4 + 255) / 256, 256>>>((const float4*)x, (float4*)xr, nx4);
        round_tf32_kernel<<<(nw4 + 255) / 256, 256>>>((const float4*)wq, (float4*)wqr, nw4);
        round_tf32_kernel<<<(nw4 + 255) / 256, 256>>>((const float4*)wk, (float4*)wkr, nw4);
        round_tf32_kernel<<<(nw4 + 255) / 256, 256>>>((const float4*)wv, (float4*)wvr, nw4);
        round_tf32_kernel<<<(nw4 + 255) / 256, 256>>>((const float4*)wo, (float4*)wor, nw4);
    }

    dim3 gg(Dm / BN, M / BM);  // (32,16)
    cudaFuncSetAttribute(gemm_mma, cudaFuncAttributeMaxDynamicSharedMemorySize, GEMM_SMEM);
    gemm_mma<<<gg, 256, GEMM_SMEM>>>(xr, wqr, qp, M, Dm, Dm);
    gemm_mma<<<gg, 256, GEMM_SMEM>>>(xr, wkr, kp, M, Dm, Dm);
    gemm_mma<<<gg, 256, GEMM_SMEM>>>(xr, wvr, vp, M, Dm, Dm);

    int rope_threads = Bz * Sq * Hh * (HDim / 2);
    rope_kernel<<<rope_threads / 256, 256>>>(qp, kp, fc, fs);

    int smem_bytes = FLASH_SMEM_FLOATS * 4;
    cudaFuncSetAttribute(flash_kernel, cudaFuncAttributeMaxDynamicSharedMemorySize,
                         smem_bytes);
    dim3 fg(Sq / 64, Bz * Hh);  // (16, 64)
    flash_kernel<<<fg, 256, smem_bytes>>>(qp, kp, vp, ap);

    gemm_mma<<<gg, 256, GEMM_SMEM>>>(ap, wor, out, M, Dm, Dm);
}

// round 9
// speedup vs baseline: 2.9229x; 1.0077x over previous
#include <cuda_runtime.h>
#include <math.h>
#include <stdint.h>

#define Bz 2
#define Sq 1024
#define Dm 4096
#define Hh 32
#define HDim 128

// Scratch (device globals: no allocation allowed in kernel_launch)
__device__ float g_q[Bz * Sq * Dm];
__device__ float g_k[Bz * Sq * Dm];
__device__ float g_v[Bz * Sq * Dm];
__device__ float g_attn[Bz * Sq * Dm];   // tf32-rounded flash output
__device__ float g_xr[Bz * Sq * Dm];     // tf32-rounded x
__device__ float g_wq[Dm * Dm];
__device__ float g_wk[Dm * Dm];
__device__ float g_wv[Dm * Dm];
__device__ float g_wo[Dm * Dm];

// ===========================================================================
// helpers
// ===========================================================================
__device__ __forceinline__ uint32_t smem_u32(const void* p) {
    uint32_t a;
    asm("{ .reg .u64 t; cvta.to.shared.u64 t, %1; cvt.u32.u64 %0, t; }" : "=r"(a) : "l"(p));
    return a;
}
__device__ __forceinline__ uint32_t f2tf32(float f) {
    uint32_t u;
    asm volatile("cvt.rna.tf32.f32 %0, %1;" : "=r"(u) : "f"(f));
    return u;
}
#define CP_ASYNC_CG(dst, src) \
    asm volatile("cp.async.cg.shared.global [%0], [%1], 16;" :: "r"(dst), "l"(src))
#define CP_ASYNC_COMMIT() asm volatile("cp.async.commit_group;" ::: "memory")
#define CP_ASYNC_WAIT(n) asm volatile("cp.async.wait_group %0;" :: "n"(n) : "memory")

__device__ __forceinline__ uint32_t lds32(uint32_t addr) {
    uint32_t v;
    asm volatile("ld.shared.b32 %0, [%1];" : "=r"(v) : "r"(addr));
    return v;
}

// ===========================================================================
// Prep: elementwise tf32 (rna) rounding
// ===========================================================================
__global__ __launch_bounds__(256) void round_tf32_kernel(const float4* __restrict__ src,
                                                         float4* __restrict__ dst, int n4) {
    int i = blockIdx.x * blockDim.x + threadIdx.x;
    if (i >= n4) return;
    float4 v = src[i];
    float4 o;
    o.x = __uint_as_float(f2tf32(v.x));
    o.y = __uint_as_float(f2tf32(v.y));
    o.z = __uint_as_float(f2tf32(v.z));
    o.w = __uint_as_float(f2tf32(v.w));
    dst[i] = o;
}

// ===========================================================================
// TF32 mma.sync GEMM with 3-stage cp.async pipeline.
// C[M,N] = A[M,K] * W[N,K]^T  (row-major, K contiguous; A,W pre-tf32-rounded)
// CTA 128m x 256n, k-tile 32 (128B rows), 8 warps (64m x 64n), m16n8k8.
// Smem chunks XOR-swizzled: chunk' = chunk ^ (row & 7)  -> conflict-free.
// ===========================================================================
#define BM 128
#define BN 256
#define BK 32
#define STAGES 3
#define STAGE_BYTES ((BM + BN) * BK * 4)      // 49152
#define GEMM_SMEM (STAGES * STAGE_BYTES)      // 147456

__global__ __launch_bounds__(256, 1) void gemm_mma(const float* __restrict__ A,
                                                   const float* __restrict__ W,
                                                   float* __restrict__ C,
                                                   int M, int N, int K) {
    extern __shared__ char smem[];
    const uint32_t sbase = smem_u32(smem);
    const int tid = threadIdx.x;
    const int wid = tid >> 5;
    const int lane = tid & 31;
    const int g = lane >> 2;     // 0..7
    const int t = lane & 3;      // 0..3
    const int warp_m = (wid & 1) * 64;     // 0,64
    const int warp_n = (wid >> 1) * 64;    // 0,64,128,192
    const int bm = blockIdx.y * BM;
    const int bn = blockIdx.x * BN;
    const int niter = K / BK;    // 128

    // per-thread load map (16B chunks)
    const int lrow = tid >> 3;        // 0..31 (+32*i)
    const int lc = tid & 7;           // chunk 0..7

    float acc[4][8][4];
#pragma unroll
    for (int mi = 0; mi < 4; mi++)
#pragma unroll
        for (int ni = 0; ni < 8; ni++)
#pragma unroll
            for (int r = 0; r < 4; r++) acc[mi][ni][r] = 0.0f;

    // ---- issue loads for ktile kt into stage s ----
    auto issue = [&](int kt, int s) {
        if (kt < niter) {
            const uint32_t sA = sbase + s * STAGE_BYTES;
            const uint32_t sB = sA + BM * 128;
            const int k0 = kt * BK;
#pragma unroll
            for (int i = 0; i < 4; i++) {
                int row = lrow + i * 32;
                uint32_t dst = sA + row * 128 + ((lc ^ (row & 7)) << 4);
                const float* src = A + (size_t)(bm + row) * K + k0 + lc * 4;
                CP_ASYNC_CG(dst, src);
            }
#pragma unroll
            for (int i = 0; i < 8; i++) {
                int row = lrow + i * 32;
                uint32_t dst = sB + row * 128 + ((lc ^ (row & 7)) << 4);
                const float* src = W + (size_t)(bn + row) * K + k0 + lc * 4;
                CP_ASYNC_CG(dst, src);
            }
        }
        CP_ASYNC_COMMIT();
    };

    // prologue: stages 0..STAGES-2
#pragma unroll
    for (int s = 0; s < STAGES - 1; s++) issue(s, s);

    int rs = 0;
    for (int kt = 0; kt < niter; kt++) {
        CP_ASYNC_WAIT(STAGES - 2);
        __syncthreads();
        // issue future stage (safe: all threads finished reading that stage)
        issue(kt + STAGES - 1, (rs + STAGES - 1 >= STAGES) ? rs - 1 : rs + STAGES - 1);

        const uint32_t sA = sbase + rs * STAGE_BYTES;
        const uint32_t sB = sA + BM * 128;
#pragma unroll
        for (int ks = 0; ks < 4; ks++) {
            const int ch0 = ks * 2;
            const int ch1 = ch0 + 1;
            const int c0 = ((ch0 ^ g) << 4) + t * 4;
            const int c1 = ((ch1 ^ g) << 4) + t * 4;
            uint32_t af[4][4];
#pragma unroll
            for (int mi = 0; mi < 4; mi++) {
                const int r0 = warp_m + mi * 16 + g;
                af[mi][0] = lds32(sA + r0 * 128 + c0);
                af[mi][1] = lds32(sA + (r0 + 8) * 128 + c0);
                af[mi][2] = lds32(sA + r0 * 128 + c1);
                af[mi][3] = lds32(sA + (r0 + 8) * 128 + c1);
            }
#pragma unroll
            for (int ni = 0; ni < 8; ni++) {
                const int rn = warp_n + ni * 8 + g;
                uint32_t b0 = lds32(sB + rn * 128 + c0);
                uint32_t b1 = lds32(sB + rn * 128 + c1);
#pragma unroll
                for (int mi = 0; mi < 4; mi++) {
                    asm volatile(
                        "mma.sync.aligned.m16n8k8.row.col.f32.tf32.tf32.f32 "
                        "{%0,%1,%2,%3}, {%4,%5,%6,%7}, {%8,%9}, {%0,%1,%2,%3};"
                        : "+f"(acc[mi][ni][0]), "+f"(acc[mi][ni][1]),
                          "+f"(acc[mi][ni][2]), "+f"(acc[mi][ni][3])
                        : "r"(af[mi][0]), "r"(af[mi][1]), "r"(af[mi][2]), "r"(af[mi][3]),
                          "r"(b0), "r"(b1));
                }
            }
        }
        if (++rs == STAGES) rs = 0;
    }

    // epilogue
#pragma unroll
    for (int mi = 0; mi < 4; mi++) {
        const int row = bm + warp_m + mi * 16 + g;
#pragma unroll
        for (int ni = 0; ni < 8; ni++) {
            const int col = bn + warp_n + ni * 8 + 2 * t;
            *(float2*)(C + (size_t)row * N + col) =
                make_float2(acc[mi][ni][0], acc[mi][ni][1]);
            *(float2*)(C + (size_t)(row + 8) * N + col) =
                make_float2(acc[mi][ni][2], acc[mi][ni][3]);
        }
    }
}

// ---------------------------------------------------------------------------
// RoPE (interleaved pairs) applied in-place to Q and K.
// ---------------------------------------------------------------------------
__global__ __launch_bounds__(256) void rope_kernel(float* __restrict__ Q,
                                                   float* __restrict__ K,
                                                   const float* __restrict__ fcos,
                                                   const float* __restrict__ fsin) {
    int idx = blockIdx.x * blockDim.x + threadIdx.x;
    if (idx >= Bz * Sq * Hh * (HDim / 2)) return;
    int p = idx & 63;
    int s = (idx >> 11) & 1023;
    int b = idx >> 21;
    int h = (idx >> 6) & 31;
    size_t base = ((size_t)(b * Sq + s)) * Dm + h * HDim + (p << 1);
    float c = fcos[s * 64 + p];
    float sn = fsin[s * 64 + p];
    float2 q = *(float2*)(Q + base);
    *(float2*)(Q + base) = make_float2(q.x * c - q.y * sn, q.x * sn + q.y * c);
    float2 k = *(float2*)(K + base);
    *(float2*)(K + base) = make_float2(k.x * c - k.y * sn, k.x * sn + k.y * c);
}

// ---------------------------------------------------------------------------
// Flash attention (fp32, causal). One CTA = (b,h, 64 q-rows). 256 threads.
// Output rounded to tf32 (rna) so the O-projection GEMM can consume raw bits.
// ---------------------------------------------------------------------------
#define FLASH_SMEM_FLOATS (128 * 68 + 128 * 68 + 64 * 132 + 64 * 68)

__global__ __launch_bounds__(256) void flash_kernel(const float* __restrict__ Q,
                                                    const float* __restrict__ K,
                                                    const float* __restrict__ V,
                                                    float* __restrict__ O) {
    extern __shared__ float sm[];
    float* Qt = sm;                 // [kk][qi] 128x68
    float* Kt = Qt + 128 * 68;      // [kk][kj] 128x68
    float* Vs = Kt + 128 * 68;      // [kj][d]  64x132
    float* Ps = Vs + 64 * 132;      // [qi][kj] 64x68

    const int bh = blockIdx.y;
    const int b = bh >> 5;
    const int h = bh & 31;
    const int q0 = blockIdx.x * 64;

    const float* Qh = Q + ((size_t)b * Sq) * Dm + h * HDim;
    const float* Kh = K + ((size_t)b * Sq) * Dm + h * HDim;
    const float* Vh = V + ((size_t)b * Sq) * Dm + h * HDim;
    float* Oh = O + ((size_t)b * Sq) * Dm + h * HDim;

    const int tid = threadIdx.x;
    const int ty = tid >> 4;
    const int tx = tid & 15;
    const float scale = 0.08838834764831844f;  // 1/sqrt(128)

    for (int idx = tid; idx < 64 * 32; idx += 256) {
        int qi = idx >> 5;
        int c4 = (idx & 31) << 2;
        float4 v = *(const float4*)(Qh + (size_t)(q0 + qi) * Dm + c4);
        Qt[(c4 + 0) * 68 + qi] = v.x;
        Qt[(c4 + 1) * 68 + qi] = v.y;
        Qt[(c4 + 2) * 68 + qi] = v.z;
        Qt[(c4 + 3) * 68 + qi] = v.w;
    }

    float m_i[4], l_i[4], acc[4][8];
#pragma unroll
    for (int i = 0; i < 4; i++) {
        m_i[i] = -1e30f;
        l_i[i] = 0.0f;
#pragma unroll
        for (int d = 0; d < 8; d++) acc[i][d] = 0.0f;
    }

    for (int kb = 0; kb <= (int)blockIdx.x; kb++) {
        const int kbase = kb * 64;
        for (int idx = tid; idx < 64 * 32; idx += 256) {
            int kj = idx >> 5;
            int c4 = (idx & 31) << 2;
            float4 vk = *(const float4*)(Kh + (size_t)(kbase + kj) * Dm + c4);
            Kt[(c4 + 0) * 68 + kj] = vk.x;
            Kt[(c4 + 1) * 68 + kj] = vk.y;
            Kt[(c4 + 2) * 68 + kj] = vk.z;
            Kt[(c4 + 3) * 68 + kj] = vk.w;
            float4 vv = *(const float4*)(Vh + (size_t)(kbase + kj) * Dm + c4);
            *(float4*)&Vs[kj * 132 + c4] = vv;
        }
        __syncthreads();

        float s[4][4];
#pragma unroll
        for (int i = 0; i < 4; i++)
#pragma unroll
            for (int j = 0; j < 4; j++) s[i][j] = 0.0f;

        for (int kk = 0; kk < 128; kk++) {
            float4 a = *(float4*)&Qt[kk * 68 + ty * 4];
            float4 bb = *(float4*)&Kt[kk * 68 + tx * 4];
            float av[4] = {a.x, a.y, a.z, a.w};
            float bv[4] = {bb.x, bb.y, bb.z, bb.w};
#pragma unroll
            for (int i = 0; i < 4; i++)
#pragma unroll
                for (int j = 0; j < 4; j++) s[i][j] = fmaf(av[i], bv[j], s[i][j]);
        }

        const bool diag = (kb == (int)blockIdx.x);
#pragma unroll
        for (int i = 0; i < 4; i++) {
            const int qi_g = q0 + ty * 4 + i;
#pragma unroll
            for (int j = 0; j < 4; j++) {
                float sv = s[i][j] * scale;
                if (diag && (kbase + tx * 4 + j) > qi_g) sv = -1e30f;
                s[i][j] = sv;
            }
            float mx = fmaxf(fmaxf(s[i][0], s[i][1]), fmaxf(s[i][2], s[i][3]));
            mx = fmaxf(mx, __shfl_xor_sync(0xffffffffu, mx, 8));
            mx = fmaxf(mx, __shfl_xor_sync(0xffffffffu, mx, 4));
            mx = fmaxf(mx, __shfl_xor_sync(0xffffffffu, mx, 2));
            mx = fmaxf(mx, __shfl_xor_sync(0xffffffffu, mx, 1));
            float mnew = fmaxf(m_i[i], mx);
            float p0 = __expf(s[i][0] - mnew);
            float p1 = __expf(s[i][1] - mnew);
            float p2 = __expf(s[i][2] - mnew);
            float p3 = __expf(s[i][3] - mnew);
            float rs = p0 + p1 + p2 + p3;
            rs += __shfl_xor_sync(0xffffffffu, rs, 8);
            rs += __shfl_xor_sync(0xffffffffu, rs, 4);
            rs += __shfl_xor_sync(0xffffffffu, rs, 2);
            rs += __shfl_xor_sync(0xffffffffu, rs, 1);
            float alpha = __expf(m_i[i] - mnew);
            l_i[i] = l_i[i] * alpha + rs;
            m_i[i] = mnew;
#pragma unroll
            for (int d = 0; d < 8; d++) acc[i][d] *= alpha;
            *(float4*)&Ps[(ty * 4 + i) * 68 + tx * 4] = make_float4(p0, p1, p2, p3);
        }
        __syncthreads();

        for (int j = 0; j < 64; j++) {
            float4 v0 = *(float4*)&Vs[j * 132 + tx * 8];
            float4 v1 = *(float4*)&Vs[j * 132 + tx * 8 + 4];
#pragma unroll
            for (int i = 0; i < 4; i++) {
                float pv = Ps[(ty * 4 + i) * 68 + j];
                acc[i][0] = fmaf(pv, v0.x, acc[i][0]);
                acc[i][1] = fmaf(pv, v0.y, acc[i][1]);
                acc[i][2] = fmaf(pv, v0.z, acc[i][2]);
                acc[i][3] = fmaf(pv, v0.w, acc[i][3]);
                acc[i][4] = fmaf(pv, v1.x, acc[i][4]);
                acc[i][5] = fmaf(pv, v1.y, acc[i][5]);
                acc[i][6] = fmaf(pv, v1.z, acc[i][6]);
                acc[i][7] = fmaf(pv, v1.w, acc[i][7]);
            }
        }
        __syncthreads();
    }

#pragma unroll
    for (int i = 0; i < 4; i++) {
        float inv = 1.0f / l_i[i];
        float* orow = Oh + (size_t)(q0 + ty * 4 + i) * Dm + tx * 8;
        float4 o0, o1;
        o0.x = __uint_as_float(f2tf32(acc[i][0] * inv));
        o0.y = __uint_as_float(f2tf32(acc[i][1] * inv));
        o0.z = __uint_as_float(f2tf32(acc[i][2] * inv));
        o0.w = __uint_as_float(f2tf32(acc[i][3] * inv));
        o1.x = __uint_as_float(f2tf32(acc[i][4] * inv));
        o1.y = __uint_as_float(f2tf32(acc[i][5] * inv));
        o1.z = __uint_as_float(f2tf32(acc[i][6] * inv));
        o1.w = __uint_as_float(f2tf32(acc[i][7] * inv));
        *(float4*)(orow) = o0;
        *(float4*)(orow + 4) = o1;
    }
}

// ---------------------------------------------------------------------------
// Launch: round inputs -> QKV proj -> RoPE -> flash -> O proj
// ---------------------------------------------------------------------------
extern "C" void kernel_launch(void* const* d_in, const int* in_sizes, int n_in,
                              void* d_out, int out_size) {
    const float* x = (const float*)d_in[0];
    const float* fc = (const float*)d_in[1];
    const float* fs = (const float*)d_in[2];
    const float* wq = (const float*)d_in[6];
    const float* wk = (const float*)d_in[7];
    const float* wv = (const float*)d_in[8];
    const float* wo = (const float*)d_in[9];
    float* out = (float*)d_out;

    float *qp, *kp, *vp, *ap, *xr, *wqr, *wkr, *wvr, *wor;
    cudaGetSymbolAddress((void**)&qp, g_q);
    cudaGetSymbolAddress((void**)&kp, g_k);
    cudaGetSymbolAddress((void**)&vp, g_v);
    cudaGetSymbolAddress((void**)&ap, g_attn);
    cudaGetSymbolAddress((void**)&xr, g_xr);
    cudaGetSymbolAddress((void**)&wqr, g_wq);
    cudaGetSymbolAddress((void**)&wkr, g_wk);
    cudaGetSymbolAddress((void**)&wvr, g_wv);
    cudaGetSymbolAddress((void**)&wor, g_wo);

    const int M = Bz * Sq;  // 2048

    // prep: tf32-round x and weights
    {
        int nx4 = (Bz * Sq * Dm) / 4;
        int nw4 = (Dm * Dm) / 4;
        round_tf32_kernel<<<(nx4 + 255) / 256, 256>>>((const float4*)x, (float4*)xr, nx4);
        round_tf32_kernel<<<(nw4 + 255) / 256, 256>>>((const float4*)wq, (float4*)wqr, nw4);
        round_tf32_kernel<<<(nw4 + 255) / 256, 256>>>((const float4*)wk, (float4*)wkr, nw4);
        round_tf32_kernel<<<(nw4 + 255) / 256, 256>>>((const float4*)wv, (float4*)wvr, nw4);
        round_tf32_kernel<<<(nw4 + 255) / 256, 256>>>((const float4*)wo, (float4*)wor, nw4);
    }

    dim3 gg(Dm / BN, M / BM);  // (16,16)
    cudaFuncSetAttribute(gemm_mma, cudaFuncAttributeMaxDynamicSharedMemorySize, GEMM_SMEM);
    gemm_mma<<<gg, 256, GEMM_SMEM>>>(xr, wqr, qp, M, Dm, Dm);
    gemm_mma<<<gg, 256, GEMM_SMEM>>>(xr, wkr, kp, M, Dm, Dm);
    gemm_mma<<<gg, 256, GEMM_SMEM>>>(xr, wvr, vp, M, Dm, Dm);

    int rope_threads = Bz * Sq * Hh * (HDim / 2);
    rope_kernel<<<rope_threads / 256, 256>>>(qp, kp, fc, fs);

    int smem_bytes = FLASH_SMEM_FLOATS * 4;
    cudaFuncSetAttribute(flash_kernel, cudaFuncAttributeMaxDynamicSharedMemorySize,
                         smem_bytes);
    dim3 fg(Sq / 64, Bz * Hh);  // (16, 64)
    flash_kernel<<<fg, 256, smem_bytes>>>(qp, kp, vp, ap);

    gemm_mma<<<gg, 256, GEMM_SMEM>>>(ap, wor, out, M, Dm, Dm);
}

// round 10
// speedup vs baseline: 3.8291x; 1.3100x over previous
#include <cuda_runtime.h>
#include <math.h>
#include <stdint.h>

#define Bz 2
#define Sq 1024
#define Dm 4096
#define Hh 32
#define HDim 128

// Scratch (device globals: no allocation allowed in kernel_launch)
__device__ float g_q[Bz * Sq * Dm];
__device__ float g_k[Bz * Sq * Dm];
__device__ float g_v[Bz * Sq * Dm];
__device__ float g_attn[Bz * Sq * Dm];   // tf32-rounded flash output
__device__ float g_xr[Bz * Sq * Dm];     // tf32-rounded x
__device__ float g_wq[Dm * Dm];
__device__ float g_wk[Dm * Dm];
__device__ float g_wv[Dm * Dm];
__device__ float g_wo[Dm * Dm];

// ===========================================================================
// helpers
// ===========================================================================
__device__ __forceinline__ uint32_t smem_u32(const void* p) {
    uint32_t a;
    asm("{ .reg .u64 t; cvta.to.shared.u64 t, %1; cvt.u32.u64 %0, t; }" : "=r"(a) : "l"(p));
    return a;
}
__device__ __forceinline__ uint32_t f2tf32(float f) {
    uint32_t u;
    asm volatile("cvt.rna.tf32.f32 %0, %1;" : "=r"(u) : "f"(f));
    return u;
}
#define CP_ASYNC_CG(dst, src) \
    asm volatile("cp.async.cg.shared.global [%0], [%1], 16;" :: "r"(dst), "l"(src))
#define CP_ASYNC_COMMIT() asm volatile("cp.async.commit_group;" ::: "memory")
#define CP_ASYNC_WAIT(n) asm volatile("cp.async.wait_group %0;" :: "n"(n) : "memory")

__device__ __forceinline__ uint32_t lds32(uint32_t addr) {
    uint32_t v;
    asm volatile("ld.shared.b32 %0, [%1];" : "=r"(v) : "r"(addr));
    return v;
}
#define MMA_TF32(d0,d1,d2,d3,a0,a1,a2,a3,b0,b1) \
    asm volatile( \
        "mma.sync.aligned.m16n8k8.row.col.f32.tf32.tf32.f32 " \
        "{%0,%1,%2,%3}, {%4,%5,%6,%7}, {%8,%9}, {%0,%1,%2,%3};" \
        : "+f"(d0), "+f"(d1), "+f"(d2), "+f"(d3) \
        : "r"(a0), "r"(a1), "r"(a2), "r"(a3), "r"(b0), "r"(b1))

// ===========================================================================
// Prep: elementwise tf32 (rna) rounding
// ===========================================================================
__global__ __launch_bounds__(256) void round_tf32_kernel(const float4* __restrict__ src,
                                                         float4* __restrict__ dst, int n4) {
    int i = blockIdx.x * blockDim.x + threadIdx.x;
    if (i >= n4) return;
    float4 v = src[i];
    float4 o;
    o.x = __uint_as_float(f2tf32(v.x));
    o.y = __uint_as_float(f2tf32(v.y));
    o.z = __uint_as_float(f2tf32(v.z));
    o.w = __uint_as_float(f2tf32(v.w));
    dst[i] = o;
}

// ===========================================================================
// TF32 mma.sync GEMM with 3-stage cp.async pipeline. (unchanged from R9)
// ===========================================================================
#define BM 128
#define BN 256
#define BK 32
#define STAGES 3
#define STAGE_BYTES ((BM + BN) * BK * 4)      // 49152
#define GEMM_SMEM (STAGES * STAGE_BYTES)      // 147456

__global__ __launch_bounds__(256, 1) void gemm_mma(const float* __restrict__ A,
                                                   const float* __restrict__ W,
                                                   float* __restrict__ C,
                                                   int M, int N, int K) {
    extern __shared__ char smem[];
    const uint32_t sbase = smem_u32(smem);
    const int tid = threadIdx.x;
    const int wid = tid >> 5;
    const int lane = tid & 31;
    const int g = lane >> 2;
    const int t = lane & 3;
    const int warp_m = (wid & 1) * 64;
    const int warp_n = (wid >> 1) * 64;
    const int bm = blockIdx.y * BM;
    const int bn = blockIdx.x * BN;
    const int niter = K / BK;

    const int lrow = tid >> 3;
    const int lc = tid & 7;

    float acc[4][8][4];
#pragma unroll
    for (int mi = 0; mi < 4; mi++)
#pragma unroll
        for (int ni = 0; ni < 8; ni++)
#pragma unroll
            for (int r = 0; r < 4; r++) acc[mi][ni][r] = 0.0f;

    auto issue = [&](int kt, int s) {
        if (kt < niter) {
            const uint32_t sA = sbase + s * STAGE_BYTES;
            const uint32_t sB = sA + BM * 128;
            const int k0 = kt * BK;
#pragma unroll
            for (int i = 0; i < 4; i++) {
                int row = lrow + i * 32;
                uint32_t dst = sA + row * 128 + ((lc ^ (row & 7)) << 4);
                const float* src = A + (size_t)(bm + row) * K + k0 + lc * 4;
                CP_ASYNC_CG(dst, src);
            }
#pragma unroll
            for (int i = 0; i < 8; i++) {
                int row = lrow + i * 32;
                uint32_t dst = sB + row * 128 + ((lc ^ (row & 7)) << 4);
                const float* src = W + (size_t)(bn + row) * K + k0 + lc * 4;
                CP_ASYNC_CG(dst, src);
            }
        }
        CP_ASYNC_COMMIT();
    };

#pragma unroll
    for (int s = 0; s < STAGES - 1; s++) issue(s, s);

    int rs = 0;
    for (int kt = 0; kt < niter; kt++) {
        CP_ASYNC_WAIT(STAGES - 2);
        __syncthreads();
        issue(kt + STAGES - 1, (rs + STAGES - 1 >= STAGES) ? rs - 1 : rs + STAGES - 1);

        const uint32_t sA = sbase + rs * STAGE_BYTES;
        const uint32_t sB = sA + BM * 128;
#pragma unroll
        for (int ks = 0; ks < 4; ks++) {
            const int ch0 = ks * 2;
            const int ch1 = ch0 + 1;
            const int c0 = ((ch0 ^ g) << 4) + t * 4;
            const int c1 = ((ch1 ^ g) << 4) + t * 4;
            uint32_t af[4][4];
#pragma unroll
            for (int mi = 0; mi < 4; mi++) {
                const int r0 = warp_m + mi * 16 + g;
                af[mi][0] = lds32(sA + r0 * 128 + c0);
                af[mi][1] = lds32(sA + (r0 + 8) * 128 + c0);
                af[mi][2] = lds32(sA + r0 * 128 + c1);
                af[mi][3] = lds32(sA + (r0 + 8) * 128 + c1);
            }
#pragma unroll
            for (int ni = 0; ni < 8; ni++) {
                const int rn = warp_n + ni * 8 + g;
                uint32_t b0 = lds32(sB + rn * 128 + c0);
                uint32_t b1 = lds32(sB + rn * 128 + c1);
#pragma unroll
                for (int mi = 0; mi < 4; mi++) {
                    MMA_TF32(acc[mi][ni][0], acc[mi][ni][1], acc[mi][ni][2], acc[mi][ni][3],
                             af[mi][0], af[mi][1], af[mi][2], af[mi][3], b0, b1);
                }
            }
        }
        if (++rs == STAGES) rs = 0;
    }

#pragma unroll
    for (int mi = 0; mi < 4; mi++) {
        const int row = bm + warp_m + mi * 16 + g;
#pragma unroll
        for (int ni = 0; ni < 8; ni++) {
            const int col = bn + warp_n + ni * 8 + 2 * t;
            *(float2*)(C + (size_t)row * N + col) =
                make_float2(acc[mi][ni][0], acc[mi][ni][1]);
            *(float2*)(C + (size_t)(row + 8) * N + col) =
                make_float2(acc[mi][ni][2], acc[mi][ni][3]);
        }
    }
}

// ---------------------------------------------------------------------------
// RoPE (interleaved pairs) applied in-place to Q and K.
// ---------------------------------------------------------------------------
__global__ __launch_bounds__(256) void rope_kernel(float* __restrict__ Q,
                                                   float* __restrict__ K,
                                                   const float* __restrict__ fcos,
                                                   const float* __restrict__ fsin) {
    int idx = blockIdx.x * blockDim.x + threadIdx.x;
    if (idx >= Bz * Sq * Hh * (HDim / 2)) return;
    int p = idx & 63;
    int s = (idx >> 11) & 1023;
    int b = idx >> 21;
    int h = (idx >> 6) & 31;
    size_t base = ((size_t)(b * Sq + s)) * Dm + h * HDim + (p << 1);
    float c = fcos[s * 64 + p];
    float sn = fsin[s * 64 + p];
    float2 q = *(float2*)(Q + base);
    *(float2*)(Q + base) = make_float2(q.x * c - q.y * sn, q.x * sn + q.y * c);
    float2 k = *(float2*)(K + base);
    *(float2*)(K + base) = make_float2(k.x * c - k.y * sn, k.x * sn + k.y * c);
}

// ===========================================================================
// Flash attention with tf32 mma (causal). CTA = (b,h, 128 q-rows), 8 warps.
// Each warp owns 16 q-rows. k-tile 64.
// Smem: Qs[128][132] tf32, Ks[64][132] tf32, Vt[128][68] tf32 (transposed),
//       Ps[128][68] tf32.  Fragment LDS bank pattern (4g+t): conflict-free.
// ===========================================================================
#define FQ 128
#define FKT 64
#define QS_STRIDE 132
#define VT_STRIDE 68
#define FLASH_SMEM ((FQ * QS_STRIDE + FKT * QS_STRIDE + HDim * VT_STRIDE + FQ * VT_STRIDE) * 4)

__global__ __launch_bounds__(256, 1) void flash_mma_kernel(const float* __restrict__ Q,
                                                           const float* __restrict__ K,
                                                           const float* __restrict__ V,
                                                           float* __restrict__ O) {
    extern __shared__ char smraw[];
    uint32_t* smf = (uint32_t*)smraw;
    uint32_t* Qs = smf;                              // [128][132]
    uint32_t* Ks = Qs + FQ * QS_STRIDE;              // [64][132]
    uint32_t* Vt = Ks + FKT * QS_STRIDE;             // [128][68]  Vt[d][k]
    uint32_t* Ps = Vt + HDim * VT_STRIDE;            // [128][68]
    const uint32_t sQ = smem_u32(Qs);
    const uint32_t sK = smem_u32(Ks);
    const uint32_t sV = smem_u32(Vt);
    const uint32_t sP = smem_u32(Ps);

    const int bh = blockIdx.y;
    const int b = bh >> 5;
    const int h = bh & 31;
    const int q0 = blockIdx.x * FQ;

    const float* Qh = Q + ((size_t)b * Sq) * Dm + h * HDim;
    const float* Kh = K + ((size_t)b * Sq) * Dm + h * HDim;
    const float* Vh = V + ((size_t)b * Sq) * Dm + h * HDim;
    float* Oh = O + ((size_t)b * Sq) * Dm + h * HDim;

    const int tid = threadIdx.x;
    const int wid = tid >> 5;
    const int lane = tid & 31;
    const int g = lane >> 2;
    const int t = lane & 3;
    const int warp_m = wid * 16;
    const float scale = 0.08838834764831844f;  // 1/sqrt(128)

    // Load Q tile once (tf32)
    for (int idx = tid; idx < FQ * 32; idx += 256) {
        int row = idx >> 5;
        int c4 = (idx & 31) << 2;
        float4 v = *(const float4*)(Qh + (size_t)(q0 + row) * Dm + c4);
        uint32_t* d = &Qs[row * QS_STRIDE + c4];
        d[0] = f2tf32(v.x); d[1] = f2tf32(v.y); d[2] = f2tf32(v.z); d[3] = f2tf32(v.w);
    }

    float m0 = -1e30f, m1 = -1e30f, l0 = 0.0f, l1 = 0.0f;
    float o[16][4];
#pragma unroll
    for (int ni = 0; ni < 16; ni++)
#pragma unroll
        for (int r = 0; r < 4; r++) o[ni][r] = 0.0f;

    const int nkt = 2 * blockIdx.x + 2;
    for (int kb = 0; kb < nkt; kb++) {
        const int kbase = kb * FKT;
        __syncthreads();   // protect Ks/Vt from previous iteration's readers
        // K tile (tf32, K-major)
        for (int idx = tid; idx < FKT * 32; idx += 256) {
            int row = idx >> 5;
            int c4 = (idx & 31) << 2;
            float4 v = *(const float4*)(Kh + (size_t)(kbase + row) * Dm + c4);
            uint32_t* d = &Ks[row * QS_STRIDE + c4];
            d[0] = f2tf32(v.x); d[1] = f2tf32(v.y); d[2] = f2tf32(v.z); d[3] = f2tf32(v.w);
        }
        // V tile transposed: Vt[d][k]
        for (int idx = tid; idx < FKT * 32; idx += 256) {
            int kj = idx >> 5;
            int c4 = (idx & 31) << 2;
            float4 v = *(const float4*)(Vh + (size_t)(kbase + kj) * Dm + c4);
            Vt[(c4 + 0) * VT_STRIDE + kj] = f2tf32(v.x);
            Vt[(c4 + 1) * VT_STRIDE + kj] = f2tf32(v.y);
            Vt[(c4 + 2) * VT_STRIDE + kj] = f2tf32(v.z);
            Vt[(c4 + 3) * VT_STRIDE + kj] = f2tf32(v.w);
        }
        __syncthreads();

        // ---- S = Q K^T (warp computes 16x64) ----
        float s[8][4];
#pragma unroll
        for (int ni = 0; ni < 8; ni++)
#pragma unroll
            for (int r = 0; r < 4; r++) s[ni][r] = 0.0f;

#pragma unroll
        for (int ks = 0; ks < 16; ks++) {
            const int kc = ks * 8;
            uint32_t a0 = lds32(sQ + ((warp_m + g) * QS_STRIDE + kc + t) * 4);
            uint32_t a1 = lds32(sQ + ((warp_m + g + 8) * QS_STRIDE + kc + t) * 4);
            uint32_t a2 = lds32(sQ + ((warp_m + g) * QS_STRIDE + kc + t + 4) * 4);
            uint32_t a3 = lds32(sQ + ((warp_m + g + 8) * QS_STRIDE + kc + t + 4) * 4);
#pragma unroll
            for (int ni = 0; ni < 8; ni++) {
                uint32_t b0 = lds32(sK + ((ni * 8 + g) * QS_STRIDE + kc + t) * 4);
                uint32_t b1 = lds32(sK + ((ni * 8 + g) * QS_STRIDE + kc + t + 4) * 4);
                MMA_TF32(s[ni][0], s[ni][1], s[ni][2], s[ni][3], a0, a1, a2, a3, b0, b1);
            }
        }

        // ---- softmax on rows r0 = q0+warp_m+g, r1 = r0+8 ----
        const int r0 = q0 + warp_m + g;
        const int r1 = r0 + 8;
        const bool diag = (kb >= 2 * (int)blockIdx.x);
        float mx0 = -1e30f, mx1 = -1e30f;
#pragma unroll
        for (int ni = 0; ni < 8; ni++) {
            const int col = kbase + ni * 8 + 2 * t;
            float v0 = s[ni][0] * scale, v1 = s[ni][1] * scale;
            float v2 = s[ni][2] * scale, v3 = s[ni][3] * scale;
            if (diag) {
                if (col > r0) v0 = -1e30f;
                if (col + 1 > r0) v1 = -1e30f;
                if (col > r1) v2 = -1e30f;
                if (col + 1 > r1) v3 = -1e30f;
            }
            s[ni][0] = v0; s[ni][1] = v1; s[ni][2] = v2; s[ni][3] = v3;
            mx0 = fmaxf(mx0, fmaxf(v0, v1));
            mx1 = fmaxf(mx1, fmaxf(v2, v3));
        }
        mx0 = fmaxf(mx0, __shfl_xor_sync(0xffffffffu, mx0, 1));
        mx0 = fmaxf(mx0, __shfl_xor_sync(0xffffffffu, mx0, 2));
        mx1 = fmaxf(mx1, __shfl_xor_sync(0xffffffffu, mx1, 1));
        mx1 = fmaxf(mx1, __shfl_xor_sync(0xffffffffu, mx1, 2));
        const float mn0 = fmaxf(m0, mx0);
        const float mn1 = fmaxf(m1, mx1);
        float rs0 = 0.0f, rs1 = 0.0f;
#pragma unroll
        for (int ni = 0; ni < 8; ni++) {
            float p0 = __expf(s[ni][0] - mn0);
            float p1 = __expf(s[ni][1] - mn0);
            float p2 = __expf(s[ni][2] - mn1);
            float p3 = __expf(s[ni][3] - mn1);
            rs0 += p0 + p1; rs1 += p2 + p3;
            const int cc = ni * 8 + 2 * t;
            Ps[(warp_m + g) * VT_STRIDE + cc] = f2tf32(p0);
            Ps[(warp_m + g) * VT_STRIDE + cc + 1] = f2tf32(p1);
            Ps[(warp_m + g + 8) * VT_STRIDE + cc] = f2tf32(p2);
            Ps[(warp_m + g + 8) * VT_STRIDE + cc + 1] = f2tf32(p3);
        }
        rs0 += __shfl_xor_sync(0xffffffffu, rs0, 1);
        rs0 += __shfl_xor_sync(0xffffffffu, rs0, 2);
        rs1 += __shfl_xor_sync(0xffffffffu, rs1, 1);
        rs1 += __shfl_xor_sync(0xffffffffu, rs1, 2);
        const float al0 = __expf(m0 - mn0);
        const float al1 = __expf(m1 - mn1);
        l0 = l0 * al0 + rs0;
        l1 = l1 * al1 + rs1;
        m0 = mn0; m1 = mn1;
#pragma unroll
        for (int ni = 0; ni < 16; ni++) {
            o[ni][0] *= al0; o[ni][1] *= al0;
            o[ni][2] *= al1; o[ni][3] *= al1;
        }
        __syncwarp();

        // ---- O += P V (warp: 16 rows x 128 d) ----
#pragma unroll
        for (int ks = 0; ks < 8; ks++) {
            const int kc = ks * 8;
            uint32_t a0 = lds32(sP + ((warp_m + g) * VT_STRIDE + kc + t) * 4);
            uint32_t a1 = lds32(sP + ((warp_m + g + 8) * VT_STRIDE + kc + t) * 4);
            uint32_t a2 = lds32(sP + ((warp_m + g) * VT_STRIDE + kc + t + 4) * 4);
            uint32_t a3 = lds32(sP + ((warp_m + g + 8) * VT_STRIDE + kc + t + 4) * 4);
#pragma unroll
            for (int ni = 0; ni < 16; ni++) {
                uint32_t b0 = lds32(sV + ((ni * 8 + g) * VT_STRIDE + kc + t) * 4);
                uint32_t b1 = lds32(sV + ((ni * 8 + g) * VT_STRIDE + kc + t + 4) * 4);
                MMA_TF32(o[ni][0], o[ni][1], o[ni][2], o[ni][3], a0, a1, a2, a3, b0, b1);
            }
        }
        __syncwarp();
    }

    // final: normalize, round to tf32, store
    const float inv0 = 1.0f / l0;
    const float inv1 = 1.0f / l1;
    const int r0 = q0 + warp_m + g;
#pragma unroll
    for (int ni = 0; ni < 16; ni++) {
        const int col = ni * 8 + 2 * t;
        float2 w0, w1;
        w0.x = __uint_as_float(f2tf32(o[ni][0] * inv0));
        w0.y = __uint_as_float(f2tf32(o[ni][1] * inv0));
        w1.x = __uint_as_float(f2tf32(o[ni][2] * inv1));
        w1.y = __uint_as_float(f2tf32(o[ni][3] * inv1));
        *(float2*)(Oh + (size_t)r0 * Dm + col) = w0;
        *(float2*)(Oh + (size_t)(r0 + 8) * Dm + col) = w1;
    }
}

// ---------------------------------------------------------------------------
// Launch: round inputs -> QKV proj -> RoPE -> flash(mma) -> O proj
// ---------------------------------------------------------------------------
extern "C" void kernel_launch(void* const* d_in, const int* in_sizes, int n_in,
                              void* d_out, int out_size) {
    const float* x = (const float*)d_in[0];
    const float* fc = (const float*)d_in[1];
    const float* fs = (const float*)d_in[2];
    const float* wq = (const float*)d_in[6];
    const float* wk = (const float*)d_in[7];
    const float* wv = (const float*)d_in[8];
    const float* wo = (const float*)d_in[9];
    float* out = (float*)d_out;

    float *qp, *kp, *vp, *ap, *xr, *wqr, *wkr, *wvr, *wor;
    cudaGetSymbolAddress((void**)&qp, g_q);
    cudaGetSymbolAddress((void**)&kp, g_k);
    cudaGetSymbolAddress((void**)&vp, g_v);
    cudaGetSymbolAddress((void**)&ap, g_attn);
    cudaGetSymbolAddress((void**)&xr, g_xr);
    cudaGetSymbolAddress((void**)&wqr, g_wq);
    cudaGetSymbolAddress((void**)&wkr, g_wk);
    cudaGetSymbolAddress((void**)&wvr, g_wv);
    cudaGetSymbolAddress((void**)&wor, g_wo);

    const int M = Bz * Sq;  // 2048

    // prep: tf32-round x and weights
    {
        int nx4 = (Bz * Sq * Dm) / 4;
        int nw4 = (Dm * Dm) / 4;
        round_tf32_kernel<<<(nx4 + 255) / 256, 256>>>((const float4*)x, (float4*)xr, nx4);
        round_tf32_kernel<<<(nw4 + 255) / 256, 256>>>((const float4*)wq, (float4*)wqr, nw4);
        round_tf32_kernel<<<(nw4 + 255) / 256, 256>>>((const float4*)wk, (float4*)wkr, nw4);
        round_tf32_kernel<<<(nw4 + 255) / 256, 256>>>((const float4*)wv, (float4*)wvr, nw4);
        round_tf32_kernel<<<(nw4 + 255) / 256, 256>>>((const float4*)wo, (float4*)wor, nw4);
    }

    dim3 gg(Dm / BN, M / BM);  // (16,16)
    cudaFuncSetAttribute(gemm_mma, cudaFuncAttributeMaxDynamicSharedMemorySize, GEMM_SMEM);
    gemm_mma<<<gg, 256, GEMM_SMEM>>>(xr, wqr, qp, M, Dm, Dm);
    gemm_mma<<<gg, 256, GEMM_SMEM>>>(xr, wkr, kp, M, Dm, Dm);
    gemm_mma<<<gg, 256, GEMM_SMEM>>>(xr, wvr, vp, M, Dm, Dm);

    int rope_threads = Bz * Sq * Hh * (HDim / 2);
    rope_kernel<<<rope_threads / 256, 256>>>(qp, kp, fc, fs);

    cudaFuncSetAttribute(flash_mma_kernel, cudaFuncAttributeMaxDynamicSharedMemorySize,
                         FLASH_SMEM);
    dim3 fg(Sq / FQ, Bz * Hh);  // (8, 64)
    flash_mma_kernel<<<fg, 256, FLASH_SMEM>>>(qp, kp, vp, ap);

    gemm_mma<<<gg, 256, GEMM_SMEM>>>(ap, wor, out, M, Dm, Dm);
}

// round 11
// speedup vs baseline: 6.2268x; 1.6262x over previous
#include <cuda_runtime.h>
#include <cuda_fp16.h>
#include <math.h>
#include <stdint.h>

#define Bz 2
#define Sq 1024
#define Dm 4096
#define Hh 32
#define HDim 128

// Scratch (device globals: no allocation allowed in kernel_launch)
__device__ float g_q[Bz * Sq * Dm];
__device__ float g_k[Bz * Sq * Dm];
__device__ float g_v[Bz * Sq * Dm];
__device__ __half g_attn_h[Bz * Sq * Dm];  // flash output, fp16
__device__ __half g_xh[Bz * Sq * Dm];      // fp16-rounded x
__device__ __half g_wqh[Dm * Dm];
__device__ __half g_wkh[Dm * Dm];
__device__ __half g_wvh[Dm * Dm];
__device__ __half g_woh[Dm * Dm];

// ===========================================================================
// helpers
// ===========================================================================
__device__ __forceinline__ uint32_t smem_u32(const void* p) {
    uint32_t a;
    asm("{ .reg .u64 t; cvta.to.shared.u64 t, %1; cvt.u32.u64 %0, t; }" : "=r"(a) : "l"(p));
    return a;
}
__device__ __forceinline__ uint32_t f2tf32(float f) {
    uint32_t u;
    asm volatile("cvt.rna.tf32.f32 %0, %1;" : "=r"(u) : "f"(f));
    return u;
}
#define CP_ASYNC_CG(dst, src) \
    asm volatile("cp.async.cg.shared.global [%0], [%1], 16;" :: "r"(dst), "l"(src))
#define CP_ASYNC_COMMIT() asm volatile("cp.async.commit_group;" ::: "memory")
#define CP_ASYNC_WAIT(n) asm volatile("cp.async.wait_group %0;" :: "n"(n) : "memory")

__device__ __forceinline__ uint32_t lds32(uint32_t addr) {
    uint32_t v;
    asm volatile("ld.shared.b32 %0, [%1];" : "=r"(v) : "r"(addr));
    return v;
}
#define MMA_TF32(d0,d1,d2,d3,a0,a1,a2,a3,b0,b1) \
    asm volatile( \
        "mma.sync.aligned.m16n8k8.row.col.f32.tf32.tf32.f32 " \
        "{%0,%1,%2,%3}, {%4,%5,%6,%7}, {%8,%9}, {%0,%1,%2,%3};" \
        : "+f"(d0), "+f"(d1), "+f"(d2), "+f"(d3) \
        : "r"(a0), "r"(a1), "r"(a2), "r"(a3), "r"(b0), "r"(b1))
#define MMA_F16(d0,d1,d2,d3,a0,a1,a2,a3,b0,b1) \
    asm volatile( \
        "mma.sync.aligned.m16n8k16.row.col.f32.f16.f16.f32 " \
        "{%0,%1,%2,%3}, {%4,%5,%6,%7}, {%8,%9}, {%0,%1,%2,%3};" \
        : "+f"(d0), "+f"(d1), "+f"(d2), "+f"(d3) \
        : "r"(a0), "r"(a1), "r"(a2), "r"(a3), "r"(b0), "r"(b1))

// ===========================================================================
// Prep: elementwise fp16 (rn) rounding, float4 -> 2x half2 (8B out)
// ===========================================================================
__global__ __launch_bounds__(256) void round_fp16_kernel(const float4* __restrict__ src,
                                                         __half2* __restrict__ dst, int n4) {
    int i = blockIdx.x * blockDim.x + threadIdx.x;
    if (i >= n4) return;
    float4 v = src[i];
    dst[i * 2 + 0] = __floats2half2_rn(v.x, v.y);
    dst[i * 2 + 1] = __floats2half2_rn(v.z, v.w);
}

// ===========================================================================
// FP16 mma.sync GEMM with 3-stage cp.async pipeline.
// C[M,N] = A[M,K] * W[N,K]^T  (row-major, K contiguous; A,W fp16)
// CTA 128m x 256n, k-tile 64 fp16 (128B rows), 8 warps (64m x 64n), m16n8k16.
// Smem 16B chunks XOR-swizzled: chunk' = chunk ^ (row & 7) -> conflict-free.
// ===========================================================================
#define BM 128
#define BN 256
#define BKH 64
#define STAGES 3
#define STAGE_BYTES ((BM + BN) * 128)         // 49152
#define GEMM_SMEM (STAGES * STAGE_BYTES)      // 147456

__global__ __launch_bounds__(256, 1) void gemm_hmma(const __half* __restrict__ A,
                                                    const __half* __restrict__ W,
                                                    float* __restrict__ C,
                                                    int M, int N, int K) {
    extern __shared__ char smem[];
    const uint32_t sbase = smem_u32(smem);
    const int tid = threadIdx.x;
    const int wid = tid >> 5;
    const int lane = tid & 31;
    const int g = lane >> 2;
    const int t = lane & 3;
    const int warp_m = (wid & 1) * 64;
    const int warp_n = (wid >> 1) * 64;
    const int bm = blockIdx.y * BM;
    const int bn = blockIdx.x * BN;
    const int niter = K / BKH;   // 64

    const int lrow = tid >> 3;
    const int lc = tid & 7;

    float acc[4][8][4];
#pragma unroll
    for (int mi = 0; mi < 4; mi++)
#pragma unroll
        for (int ni = 0; ni < 8; ni++)
#pragma unroll
            for (int r = 0; r < 4; r++) acc[mi][ni][r] = 0.0f;

    auto issue = [&](int kt, int s) {
        if (kt < niter) {
            const uint32_t sA = sbase + s * STAGE_BYTES;
            const uint32_t sB = sA + BM * 128;
            const int k0 = kt * BKH;
#pragma unroll
            for (int i = 0; i < 4; i++) {
                int row = lrow + i * 32;
                uint32_t dst = sA + row * 128 + ((lc ^ (row & 7)) << 4);
                const __half* src = A + (size_t)(bm + row) * K + k0 + lc * 8;
                CP_ASYNC_CG(dst, src);
            }
#pragma unroll
            for (int i = 0; i < 8; i++) {
                int row = lrow + i * 32;
                uint32_t dst = sB + row * 128 + ((lc ^ (row & 7)) << 4);
                const __half* src = W + (size_t)(bn + row) * K + k0 + lc * 8;
                CP_ASYNC_CG(dst, src);
            }
        }
        CP_ASYNC_COMMIT();
    };

#pragma unroll
    for (int s = 0; s < STAGES - 1; s++) issue(s, s);

    int rs = 0;
    for (int kt = 0; kt < niter; kt++) {
        CP_ASYNC_WAIT(STAGES - 2);
        __syncthreads();
        issue(kt + STAGES - 1, (rs + STAGES - 1 >= STAGES) ? rs - 1 : rs + STAGES - 1);

        const uint32_t sA = sbase + rs * STAGE_BYTES;
        const uint32_t sB = sA + BM * 128;
#pragma unroll
        for (int ks = 0; ks < 4; ks++) {
            // k16 step ks covers chunks 2ks (k 0-7) and 2ks+1 (k 8-15)
            const int c0 = (((2 * ks) ^ g) << 4) + t * 4;
            const int c1 = (((2 * ks + 1) ^ g) << 4) + t * 4;
            uint32_t af[4][4];
#pragma unroll
            for (int mi = 0; mi < 4; mi++) {
                const int r0 = warp_m + mi * 16 + g;
                af[mi][0] = lds32(sA + r0 * 128 + c0);        // (g,   2t..2t+1)
                af[mi][1] = lds32(sA + (r0 + 8) * 128 + c0);  // (g+8, 2t..2t+1)
                af[mi][2] = lds32(sA + r0 * 128 + c1);        // (g,   8+2t..)
                af[mi][3] = lds32(sA + (r0 + 8) * 128 + c1);  // (g+8, 8+2t..)
            }
#pragma unroll
            for (int ni = 0; ni < 8; ni++) {
                const int rn = warp_n + ni * 8 + g;
                uint32_t b0 = lds32(sB + rn * 128 + c0);
                uint32_t b1 = lds32(sB + rn * 128 + c1);
#pragma unroll
                for (int mi = 0; mi < 4; mi++) {
                    MMA_F16(acc[mi][ni][0], acc[mi][ni][1], acc[mi][ni][2], acc[mi][ni][3],
                            af[mi][0], af[mi][1], af[mi][2], af[mi][3], b0, b1);
                }
            }
        }
        if (++rs == STAGES) rs = 0;
    }

#pragma unroll
    for (int mi = 0; mi < 4; mi++) {
        const int row = bm + warp_m + mi * 16 + g;
#pragma unroll
        for (int ni = 0; ni < 8; ni++) {
            const int col = bn + warp_n + ni * 8 + 2 * t;
            *(float2*)(C + (size_t)row * N + col) =
                make_float2(acc[mi][ni][0], acc[mi][ni][1]);
            *(float2*)(C + (size_t)(row + 8) * N + col) =
                make_float2(acc[mi][ni][2], acc[mi][ni][3]);
        }
    }
}

// ---------------------------------------------------------------------------
// RoPE (interleaved pairs) applied in-place to Q and K (fp32).
// ---------------------------------------------------------------------------
__global__ __launch_bounds__(256) void rope_kernel(float* __restrict__ Q,
                                                   float* __restrict__ K,
                                                   const float* __restrict__ fcos,
                                                   const float* __restrict__ fsin) {
    int idx = blockIdx.x * blockDim.x + threadIdx.x;
    if (idx >= Bz * Sq * Hh * (HDim / 2)) return;
    int p = idx & 63;
    int s = (idx >> 11) & 1023;
    int b = idx >> 21;
    int h = (idx >> 6) & 31;
    size_t base = ((size_t)(b * Sq + s)) * Dm + h * HDim + (p << 1);
    float c = fcos[s * 64 + p];
    float sn = fsin[s * 64 + p];
    float2 q = *(float2*)(Q + base);
    *(float2*)(Q + base) = make_float2(q.x * c - q.y * sn, q.x * sn + q.y * c);
    float2 k = *(float2*)(K + base);
    *(float2*)(K + base) = make_float2(k.x * c - k.y * sn, k.x * sn + k.y * c);
}

// ===========================================================================
// Flash attention with tf32 mma (causal). CTA = (b,h, 128 q-rows), 8 warps.
// (unchanged internals from R10; epilogue now writes fp16 for the O-proj)
// ===========================================================================
#define FQ 128
#define FKT 64
#define QS_STRIDE 132
#define VT_STRIDE 68
#define FLASH_SMEM ((FQ * QS_STRIDE + FKT * QS_STRIDE + HDim * VT_STRIDE + FQ * VT_STRIDE) * 4)

__global__ __launch_bounds__(256, 1) void flash_mma_kernel(const float* __restrict__ Q,
                                                           const float* __restrict__ K,
                                                           const float* __restrict__ V,
                                                           __half* __restrict__ O) {
    extern __shared__ char smraw[];
    uint32_t* smf = (uint32_t*)smraw;
    uint32_t* Qs = smf;                              // [128][132]
    uint32_t* Ks = Qs + FQ * QS_STRIDE;              // [64][132]
    uint32_t* Vt = Ks + FKT * QS_STRIDE;             // [128][68]  Vt[d][k]
    uint32_t* Ps = Vt + HDim * VT_STRIDE;            // [128][68]
    const uint32_t sQ = smem_u32(Qs);
    const uint32_t sK = smem_u32(Ks);
    const uint32_t sV = smem_u32(Vt);
    const uint32_t sP = smem_u32(Ps);

    const int bh = blockIdx.y;
    const int b = bh >> 5;
    const int h = bh & 31;
    const int q0 = blockIdx.x * FQ;

    const float* Qh = Q + ((size_t)b * Sq) * Dm + h * HDim;
    const float* Kh = K + ((size_t)b * Sq) * Dm + h * HDim;
    const float* Vh = V + ((size_t)b * Sq) * Dm + h * HDim;
    __half* Oh = O + ((size_t)b * Sq) * Dm + h * HDim;

    const int tid = threadIdx.x;
    const int wid = tid >> 5;
    const int lane = tid & 31;
    const int g = lane >> 2;
    const int t = lane & 3;
    const int warp_m = wid * 16;
    const float scale = 0.08838834764831844f;  // 1/sqrt(128)

    for (int idx = tid; idx < FQ * 32; idx += 256) {
        int row = idx >> 5;
        int c4 = (idx & 31) << 2;
        float4 v = *(const float4*)(Qh + (size_t)(q0 + row) * Dm + c4);
        uint32_t* d = &Qs[row * QS_STRIDE + c4];
        d[0] = f2tf32(v.x); d[1] = f2tf32(v.y); d[2] = f2tf32(v.z); d[3] = f2tf32(v.w);
    }

    float m0 = -1e30f, m1 = -1e30f, l0 = 0.0f, l1 = 0.0f;
    float o[16][4];
#pragma unroll
    for (int ni = 0; ni < 16; ni++)
#pragma unroll
        for (int r = 0; r < 4; r++) o[ni][r] = 0.0f;

    const int nkt = 2 * blockIdx.x + 2;
    for (int kb = 0; kb < nkt; kb++) {
        const int kbase = kb * FKT;
        __syncthreads();
        for (int idx = tid; idx < FKT * 32; idx += 256) {
            int row = idx >> 5;
            int c4 = (idx & 31) << 2;
            float4 v = *(const float4*)(Kh + (size_t)(kbase + row) * Dm + c4);
            uint32_t* d = &Ks[row * QS_STRIDE + c4];
            d[0] = f2tf32(v.x); d[1] = f2tf32(v.y); d[2] = f2tf32(v.z); d[3] = f2tf32(v.w);
        }
        for (int idx = tid; idx < FKT * 32; idx += 256) {
            int kj = idx >> 5;
            int c4 = (idx & 31) << 2;
            float4 v = *(const float4*)(Vh + (size_t)(kbase + kj) * Dm + c4);
            Vt[(c4 + 0) * VT_STRIDE + kj] = f2tf32(v.x);
            Vt[(c4 + 1) * VT_STRIDE + kj] = f2tf32(v.y);
            Vt[(c4 + 2) * VT_STRIDE + kj] = f2tf32(v.z);
            Vt[(c4 + 3) * VT_STRIDE + kj] = f2tf32(v.w);
        }
        __syncthreads();

        float s[8][4];
#pragma unroll
        for (int ni = 0; ni < 8; ni++)
#pragma unroll
            for (int r = 0; r < 4; r++) s[ni][r] = 0.0f;

#pragma unroll
        for (int ks = 0; ks < 16; ks++) {
            const int kc = ks * 8;
            uint32_t a0 = lds32(sQ + ((warp_m + g) * QS_STRIDE + kc + t) * 4);
            uint32_t a1 = lds32(sQ + ((warp_m + g + 8) * QS_STRIDE + kc + t) * 4);
            uint32_t a2 = lds32(sQ + ((warp_m + g) * QS_STRIDE + kc + t + 4) * 4);
            uint32_t a3 = lds32(sQ + ((warp_m + g + 8) * QS_STRIDE + kc + t + 4) * 4);
#pragma unroll
            for (int ni = 0; ni < 8; ni++) {
                uint32_t b0 = lds32(sK + ((ni * 8 + g) * QS_STRIDE + kc + t) * 4);
                uint32_t b1 = lds32(sK + ((ni * 8 + g) * QS_STRIDE + kc + t + 4) * 4);
                MMA_TF32(s[ni][0], s[ni][1], s[ni][2], s[ni][3], a0, a1, a2, a3, b0, b1);
            }
        }

        const int r0 = q0 + warp_m + g;
        const int r1 = r0 + 8;
        const bool diag = (kb >= 2 * (int)blockIdx.x);
        float mx0 = -1e30f, mx1 = -1e30f;
#pragma unroll
        for (int ni = 0; ni < 8; ni++) {
            const int col = kbase + ni * 8 + 2 * t;
            float v0 = s[ni][0] * scale, v1 = s[ni][1] * scale;
            float v2 = s[ni][2] * scale, v3 = s[ni][3] * scale;
            if (diag) {
                if (col > r0) v0 = -1e30f;
                if (col + 1 > r0) v1 = -1e30f;
                if (col > r1) v2 = -1e30f;
                if (col + 1 > r1) v3 = -1e30f;
            }
            s[ni][0] = v0; s[ni][1] = v1; s[ni][2] = v2; s[ni][3] = v3;
            mx0 = fmaxf(mx0, fmaxf(v0, v1));
            mx1 = fmaxf(mx1, fmaxf(v2, v3));
        }
        mx0 = fmaxf(mx0, __shfl_xor_sync(0xffffffffu, mx0, 1));
        mx0 = fmaxf(mx0, __shfl_xor_sync(0xffffffffu, mx0, 2));
        mx1 = fmaxf(mx1, __shfl_xor_sync(0xffffffffu, mx1, 1));
        mx1 = fmaxf(mx1, __shfl_xor_sync(0xffffffffu, mx1, 2));
        const float mn0 = fmaxf(m0, mx0);
        const float mn1 = fmaxf(m1, mx1);
        float rs0 = 0.0f, rs1 = 0.0f;
#pragma unroll
        for (int ni = 0; ni < 8; ni++) {
            float p0 = __expf(s[ni][0] - mn0);
            float p1 = __expf(s[ni][1] - mn0);
            float p2 = __expf(s[ni][2] - mn1);
            float p3 = __expf(s[ni][3] - mn1);
            rs0 += p0 + p1; rs1 += p2 + p3;
            const int cc = ni * 8 + 2 * t;
            Ps[(warp_m + g) * VT_STRIDE + cc] = f2tf32(p0);
            Ps[(warp_m + g) * VT_STRIDE + cc + 1] = f2tf32(p1);
            Ps[(warp_m + g + 8) * VT_STRIDE + cc] = f2tf32(p2);
            Ps[(warp_m + g + 8) * VT_STRIDE + cc + 1] = f2tf32(p3);
        }
        rs0 += __shfl_xor_sync(0xffffffffu, rs0, 1);
        rs0 += __shfl_xor_sync(0xffffffffu, rs0, 2);
        rs1 += __shfl_xor_sync(0xffffffffu, rs1, 1);
        rs1 += __shfl_xor_sync(0xffffffffu, rs1, 2);
        const float al0 = __expf(m0 - mn0);
        const float al1 = __expf(m1 - mn1);
        l0 = l0 * al0 + rs0;
        l1 = l1 * al1 + rs1;
        m0 = mn0; m1 = mn1;
#pragma unroll
        for (int ni = 0; ni < 16; ni++) {
            o[ni][0] *= al0; o[ni][1] *= al0;
            o[ni][2] *= al1; o[ni][3] *= al1;
        }
        __syncwarp();

#pragma unroll
        for (int ks = 0; ks < 8; ks++) {
            const int kc = ks * 8;
            uint32_t a0 = lds32(sP + ((warp_m + g) * VT_STRIDE + kc + t) * 4);
            uint32_t a1 = lds32(sP + ((warp_m + g + 8) * VT_STRIDE + kc + t) * 4);
            uint32_t a2 = lds32(sP + ((warp_m + g) * VT_STRIDE + kc + t + 4) * 4);
            uint32_t a3 = lds32(sP + ((warp_m + g + 8) * VT_STRIDE + kc + t + 4) * 4);
#pragma unroll
            for (int ni = 0; ni < 16; ni++) {
                uint32_t b0 = lds32(sV + ((ni * 8 + g) * VT_STRIDE + kc + t) * 4);
                uint32_t b1 = lds32(sV + ((ni * 8 + g) * VT_STRIDE + kc + t + 4) * 4);
                MMA_TF32(o[ni][0], o[ni][1], o[ni][2], o[ni][3], a0, a1, a2, a3, b0, b1);
            }
        }
        __syncwarp();
    }

    // final: normalize, round to fp16, store (feeds fp16 O-projection)
    const float inv0 = 1.0f / l0;
    const float inv1 = 1.0f / l1;
    const int r0 = q0 + warp_m + g;
#pragma unroll
    for (int ni = 0; ni < 16; ni++) {
        const int col = ni * 8 + 2 * t;
        *(__half2*)(Oh + (size_t)r0 * Dm + col) =
            __floats2half2_rn(o[ni][0] * inv0, o[ni][1] * inv0);
        *(__half2*)(Oh + (size_t)(r0 + 8) * Dm + col) =
            __floats2half2_rn(o[ni][2] * inv1, o[ni][3] * inv1);
    }
}

// ---------------------------------------------------------------------------
// Launch: round(fp16) inputs -> QKV proj -> RoPE -> flash -> O proj
// ---------------------------------------------------------------------------
extern "C" void kernel_launch(void* const* d_in, const int* in_sizes, int n_in,
                              void* d_out, int out_size) {
    const float* x = (const float*)d_in[0];
    const float* fc = (const float*)d_in[1];
    const float* fs = (const float*)d_in[2];
    const float* wq = (const float*)d_in[6];
    const float* wk = (const float*)d_in[7];
    const float* wv = (const float*)d_in[8];
    const float* wo = (const float*)d_in[9];
    float* out = (float*)d_out;

    float *qp, *kp, *vp;
    __half *ah, *xh, *wqh, *wkh, *wvh, *woh;
    cudaGetSymbolAddress((void**)&qp, g_q);
    cudaGetSymbolAddress((void**)&kp, g_k);
    cudaGetSymbolAddress((void**)&vp, g_v);
    cudaGetSymbolAddress((void**)&ah, g_attn_h);
    cudaGetSymbolAddress((void**)&xh, g_xh);
    cudaGetSymbolAddress((void**)&wqh, g_wqh);
    cudaGetSymbolAddress((void**)&wkh, g_wkh);
    cudaGetSymbolAddress((void**)&wvh, g_wvh);
    cudaGetSymbolAddress((void**)&woh, g_woh);

    const int M = Bz * Sq;  // 2048

    // prep: fp16-round x and weights
    {
        int nx4 = (Bz * Sq * Dm) / 4;
        int nw4 = (Dm * Dm) / 4;
        round_fp16_kernel<<<(nx4 + 255) / 256, 256>>>((const float4*)x, (__half2*)xh, nx4);
        round_fp16_kernel<<<(nw4 + 255) / 256, 256>>>((const float4*)wq, (__half2*)wqh, nw4);
        round_fp16_kernel<<<(nw4 + 255) / 256, 256>>>((const float4*)wk, (__half2*)wkh, nw4);
        round_fp16_kernel<<<(nw4 + 255) / 256, 256>>>((const float4*)wv, (__half2*)wvh, nw4);
        round_fp16_kernel<<<(nw4 + 255) / 256, 256>>>((const float4*)wo, (__half2*)woh, nw4);
    }

    dim3 gg(Dm / BN, M / BM);  // (16,16)
    cudaFuncSetAttribute(gemm_hmma, cudaFuncAttributeMaxDynamicSharedMemorySize, GEMM_SMEM);
    gemm_hmma<<<gg, 256, GEMM_SMEM>>>(xh, wqh, qp, M, Dm, Dm);
    gemm_hmma<<<gg, 256, GEMM_SMEM>>>(xh, wkh, kp, M, Dm, Dm);
    gemm_hmma<<<gg, 256, GEMM_SMEM>>>(xh, wvh, vp, M, Dm, Dm);

    int rope_threads = Bz * Sq * Hh * (HDim / 2);
    rope_kernel<<<rope_threads / 256, 256>>>(qp, kp, fc, fs);

    cudaFuncSetAttribute(flash_mma_kernel, cudaFuncAttributeMaxDynamicSharedMemorySize,
                         FLASH_SMEM);
    dim3 fg(Sq / FQ, Bz * Hh);  // (8, 64)
    flash_mma_kernel<<<fg, 256, FLASH_SMEM>>>(qp, kp, vp, ah);

    gemm_hmma<<<gg, 256, GEMM_SMEM>>>(ah, woh, out, M, Dm, Dm);
}

// round 15
// speedup vs baseline: 7.0136x; 1.1264x over previous
#include <cuda_runtime.h>
#include <cuda_fp16.h>
#include <math.h>
#include <stdint.h>

#define Bz 2
#define Sq 1024
#define Dm 4096
#define Hh 32
#define HDim 128

// Scratch (device globals: no allocation allowed in kernel_launch)
__device__ float g_q[Bz * Sq * Dm];
__device__ float g_k[Bz * Sq * Dm];
__device__ float g_v[Bz * Sq * Dm];
__device__ __half g_attn_h[Bz * Sq * Dm];  // flash output, fp16
__device__ __half g_xh[Bz * Sq * Dm];      // fp16-rounded x
__device__ __half g_wqh[Dm * Dm];
__device__ __half g_wkh[Dm * Dm];
__device__ __half g_wvh[Dm * Dm];
__device__ __half g_woh[Dm * Dm];

// ===========================================================================
// helpers
// ===========================================================================
__device__ __forceinline__ uint32_t smem_u32(const void* p) {
    uint32_t a;
    asm("{ .reg .u64 t; cvta.to.shared.u64 t, %1; cvt.u32.u64 %0, t; }" : "=r"(a) : "l"(p));
    return a;
}
#define CP_ASYNC_CG(dst, src) \
    asm volatile("cp.async.cg.shared.global [%0], [%1], 16;" :: "r"(dst), "l"(src))
#define CP_ASYNC_COMMIT() asm volatile("cp.async.commit_group;" ::: "memory")
#define CP_ASYNC_WAIT(n) asm volatile("cp.async.wait_group %0;" :: "n"(n) : "memory")

__device__ __forceinline__ uint32_t lds32(uint32_t addr) {
    uint32_t v;
    asm volatile("ld.shared.b32 %0, [%1];" : "=r"(v) : "r"(addr));
    return v;
}
#define MMA_F16(d0,d1,d2,d3,a0,a1,a2,a3,b0,b1) \
    asm volatile( \
        "mma.sync.aligned.m16n8k16.row.col.f32.f16.f16.f32 " \
        "{%0,%1,%2,%3}, {%4,%5,%6,%7}, {%8,%9}, {%0,%1,%2,%3};" \
        : "+f"(d0), "+f"(d1), "+f"(d2), "+f"(d3) \
        : "r"(a0), "r"(a1), "r"(a2), "r"(a3), "r"(b0), "r"(b1))

__device__ __forceinline__ uint32_t pack_h2(float a, float b) {
    __half2 h = __floats2half2_rn(a, b);
    return *(uint32_t*)&h;
}

// ===========================================================================
// Prep: elementwise fp16 (rn) rounding, float4 -> 2x half2 (8B out)
// ===========================================================================
__global__ __launch_bounds__(256) void round_fp16_kernel(const float4* __restrict__ src,
                                                         __half2* __restrict__ dst, int n4) {
    int i = blockIdx.x * blockDim.x + threadIdx.x;
    if (i >= n4) return;
    float4 v = src[i];
    dst[i * 2 + 0] = __floats2half2_rn(v.x, v.y);
    dst[i * 2 + 1] = __floats2half2_rn(v.z, v.w);
}

// ===========================================================================
// FP16 mma.sync GEMM with 3-stage cp.async pipeline.
// C[z][M,N] = A[M,K] * W[z][N,K]^T   — blockIdx.z selects (W, C) (QKV fused).
// CTA 128m x 256n, k-tile 64 fp16 (128B rows), 8 warps (64m x 64n), m16n8k16.
// ===========================================================================
#define BM 128
#define BN 256
#define BKH 64
#define STAGES 3
#define STAGE_BYTES ((BM + BN) * 128)         // 49152
#define GEMM_SMEM (STAGES * STAGE_BYTES)      // 147456

__global__ __launch_bounds__(256, 1) void gemm_hmma(const __half* __restrict__ A,
                                                    const __half* __restrict__ W0,
                                                    const __half* __restrict__ W1,
                                                    const __half* __restrict__ W2,
                                                    float* __restrict__ C0,
                                                    float* __restrict__ C1,
                                                    float* __restrict__ C2,
                                                    int M, int N, int K) {
    const __half* W = (blockIdx.z == 0) ? W0 : (blockIdx.z == 1) ? W1 : W2;
    float* C = (blockIdx.z == 0) ? C0 : (blockIdx.z == 1) ? C1 : C2;

    extern __shared__ char smem[];
    const uint32_t sbase = smem_u32(smem);
    const int tid = threadIdx.x;
    const int wid = tid >> 5;
    const int lane = tid & 31;
    const int g = lane >> 2;
    const int t = lane & 3;
    const int warp_m = (wid & 1) * 64;
    const int warp_n = (wid >> 1) * 64;
    const int bm = blockIdx.y * BM;
    const int bn = blockIdx.x * BN;
    const int niter = K / BKH;   // 64

    const int lrow = tid >> 3;
    const int lc = tid & 7;

    float acc[4][8][4];
#pragma unroll
    for (int mi = 0; mi < 4; mi++)
#pragma unroll
        for (int ni = 0; ni < 8; ni++)
#pragma unroll
            for (int r = 0; r < 4; r++) acc[mi][ni][r] = 0.0f;

    auto issue = [&](int kt, int s) {
        if (kt < niter) {
            const uint32_t sA = sbase + s * STAGE_BYTES;
            const uint32_t sB = sA + BM * 128;
            const int k0 = kt * BKH;
#pragma unroll
            for (int i = 0; i < 4; i++) {
                int row = lrow + i * 32;
                uint32_t dst = sA + row * 128 + ((lc ^ (row & 7)) << 4);
                const __half* src = A + (size_t)(bm + row) * K + k0 + lc * 8;
                CP_ASYNC_CG(dst, src);
            }
#pragma unroll
            for (int i = 0; i < 8; i++) {
                int row = lrow + i * 32;
                uint32_t dst = sB + row * 128 + ((lc ^ (row & 7)) << 4);
                const __half* src = W + (size_t)(bn + row) * K + k0 + lc * 8;
                CP_ASYNC_CG(dst, src);
            }
        }
        CP_ASYNC_COMMIT();
    };

#pragma unroll
    for (int s = 0; s < STAGES - 1; s++) issue(s, s);

    int rs = 0;
    for (int kt = 0; kt < niter; kt++) {
        CP_ASYNC_WAIT(STAGES - 2);
        __syncthreads();
        issue(kt + STAGES - 1, (rs + STAGES - 1 >= STAGES) ? rs - 1 : rs + STAGES - 1);

        const uint32_t sA = sbase + rs * STAGE_BYTES;
        const uint32_t sB = sA + BM * 128;
#pragma unroll
        for (int ks = 0; ks < 4; ks++) {
            const int c0 = (((2 * ks) ^ g) << 4) + t * 4;
            const int c1 = (((2 * ks + 1) ^ g) << 4) + t * 4;
            uint32_t af[4][4];
#pragma unroll
            for (int mi = 0; mi < 4; mi++) {
                const int r0 = warp_m + mi * 16 + g;
                af[mi][0] = lds32(sA + r0 * 128 + c0);
                af[mi][1] = lds32(sA + (r0 + 8) * 128 + c0);
                af[mi][2] = lds32(sA + r0 * 128 + c1);
                af[mi][3] = lds32(sA + (r0 + 8) * 128 + c1);
            }
#pragma unroll
            for (int ni = 0; ni < 8; ni++) {
                const int rn = warp_n + ni * 8 + g;
                uint32_t b0 = lds32(sB + rn * 128 + c0);
                uint32_t b1 = lds32(sB + rn * 128 + c1);
#pragma unroll
                for (int mi = 0; mi < 4; mi++) {
                    MMA_F16(acc[mi][ni][0], acc[mi][ni][1], acc[mi][ni][2], acc[mi][ni][3],
                            af[mi][0], af[mi][1], af[mi][2], af[mi][3], b0, b1);
                }
            }
        }
        if (++rs == STAGES) rs = 0;
    }

#pragma unroll
    for (int mi = 0; mi < 4; mi++) {
        const int row = bm + warp_m + mi * 16 + g;
#pragma unroll
        for (int ni = 0; ni < 8; ni++) {
            const int col = bn + warp_n + ni * 8 + 2 * t;
            *(float2*)(C + (size_t)row * N + col) =
                make_float2(acc[mi][ni][0], acc[mi][ni][1]);
            *(float2*)(C + (size_t)(row + 8) * N + col) =
                make_float2(acc[mi][ni][2], acc[mi][ni][3]);
        }
    }
}

// ===========================================================================
// Flash attention, fp16 mma, RoPE fused into Q/K loads. Causal.
// CTA = (b,h, 128 q-rows), 8 warps (16 q-rows each), k-tile 64.
// Smem (half2 units): Qs[128][68], Ks[64][68], Vt[128][36] (V^T), Ps[128][36].
// Fragment bank pattern (4g+t): conflict-free.
// ===========================================================================
#define FQ 128
#define FKT 64
#define QS_U 68
#define PT_U 36
#define FLASH_SMEM ((FQ * QS_U + FKT * QS_U + HDim * PT_U + FQ * PT_U) * 4)  // 89088

__global__ __launch_bounds__(256, 2) void flash_h_kernel(const float* __restrict__ Q,
                                                         const float* __restrict__ K,
                                                         const float* __restrict__ V,
                                                         const float* __restrict__ fcos,
                                                         const float* __restrict__ fsin,
                                                         __half* __restrict__ O) {
    extern __shared__ char smraw[];
    uint32_t* Qs = (uint32_t*)smraw;                 // [128][68]
    uint32_t* Ks = Qs + FQ * QS_U;                   // [64][68]
    uint32_t* Vt = Ks + FKT * QS_U;                  // [128][36]  Vt[d][k-half2]
    uint32_t* Ps = Vt + HDim * PT_U;                 // [128][36]
    const uint32_t sQ = smem_u32(Qs);
    const uint32_t sK = smem_u32(Ks);
    const uint32_t sV = smem_u32(Vt);
    const uint32_t sP = smem_u32(Ps);

    const int bh = blockIdx.y;
    const int b = bh >> 5;
    const int h = bh & 31;
    const int q0 = blockIdx.x * FQ;

    const float* Qh = Q + ((size_t)b * Sq) * Dm + h * HDim;
    const float* Kh = K + ((size_t)b * Sq) * Dm + h * HDim;
    const float* Vh = V + ((size_t)b * Sq) * Dm + h * HDim;
    __half* Oh = O + ((size_t)b * Sq) * Dm + h * HDim;

    const int tid = threadIdx.x;
    const int wid = tid >> 5;
    const int lane = tid & 31;
    const int g = lane >> 2;
    const int t = lane & 3;
    const int warp_m = wid * 16;
    const float scale = 0.08838834764831844f;  // 1/sqrt(128)

    // Load Q tile once, applying RoPE (pairs are adjacent within the float4)
    for (int idx = tid; idx < FQ * 32; idx += 256) {
        int row = idx >> 5;              // q row in tile
        int c4 = (idx & 31) << 2;        // dim offset (pairs c4/2, c4/2+1)
        int s = q0 + row;
        float4 v = *(const float4*)(Qh + (size_t)s * Dm + c4);
        int p = c4 >> 1;
        float c0 = fcos[s * 64 + p], s0 = fsin[s * 64 + p];
        float c1 = fcos[s * 64 + p + 1], s1 = fsin[s * 64 + p + 1];
        Qs[row * QS_U + p] = pack_h2(v.x * c0 - v.y * s0, v.x * s0 + v.y * c0);
        Qs[row * QS_U + p + 1] = pack_h2(v.z * c1 - v.w * s1, v.z * s1 + v.w * c1);
    }

    float m0 = -1e30f, m1 = -1e30f, l0 = 0.0f, l1 = 0.0f;
    float o[16][4];
#pragma unroll
    for (int ni = 0; ni < 16; ni++)
#pragma unroll
        for (int r = 0; r < 4; r++) o[ni][r] = 0.0f;

    const int nkt = 2 * blockIdx.x + 2;
    for (int kb = 0; kb < nkt; kb++) {
        const int kbase = kb * FKT;
        __syncthreads();
        // K tile with RoPE
        for (int idx = tid; idx < FKT * 32; idx += 256) {
            int row = idx >> 5;
            int c4 = (idx & 31) << 2;
            int s = kbase + row;
            float4 v = *(const float4*)(Kh + (size_t)s * Dm + c4);
            int p = c4 >> 1;
            float c0 = fcos[s * 64 + p], s0 = fsin[s * 64 + p];
            float c1 = fcos[s * 64 + p + 1], s1 = fsin[s * 64 + p + 1];
            Ks[row * QS_U + p] = pack_h2(v.x * c0 - v.y * s0, v.x * s0 + v.y * c0);
            Ks[row * QS_U + p + 1] = pack_h2(v.z * c1 - v.w * s1, v.z * s1 + v.w * c1);
        }
        // V tile transposed into half2-over-k: Vt[d][kj2] = (V[2kj2][d], V[2kj2+1][d])
        for (int idx = tid; idx < 32 * 32; idx += 256) {
            int kj2 = idx >> 5;              // k pair index 0..31
            int c4 = (idx & 31) << 2;        // dim offset
            const float* r0p = Vh + (size_t)(kbase + 2 * kj2) * Dm + c4;
            const float* r1p = Vh + (size_t)(kbase + 2 * kj2 + 1) * Dm + c4;
            float4 v0 = *(const float4*)r0p;
            float4 v1 = *(const float4*)r1p;
            Vt[(c4 + 0) * PT_U + kj2] = pack_h2(v0.x, v1.x);
            Vt[(c4 + 1) * PT_U + kj2] = pack_h2(v0.y, v1.y);
            Vt[(c4 + 2) * PT_U + kj2] = pack_h2(v0.z, v1.z);
            Vt[(c4 + 3) * PT_U + kj2] = pack_h2(v0.w, v1.w);
        }
        __syncthreads();

        // ---- S = Q K^T : 8 k16 steps over 128 dims ----
        float s[8][4];
#pragma unroll
        for (int ni = 0; ni < 8; ni++)
#pragma unroll
            for (int r = 0; r < 4; r++) s[ni][r] = 0.0f;

#pragma unroll
        for (int ks = 0; ks < 8; ks++) {
            const int kc = ks * 8;   // half2 col base
            uint32_t a0 = lds32(sQ + ((warp_m + g) * QS_U + kc + t) * 4);
            uint32_t a1 = lds32(sQ + ((warp_m + g + 8) * QS_U + kc + t) * 4);
            uint32_t a2 = lds32(sQ + ((warp_m + g) * QS_U + kc + 4 + t) * 4);
            uint32_t a3 = lds32(sQ + ((warp_m + g + 8) * QS_U + kc + 4 + t) * 4);
#pragma unroll
            for (int ni = 0; ni < 8; ni++) {
                uint32_t b0 = lds32(sK + ((ni * 8 + g) * QS_U + kc + t) * 4);
                uint32_t b1 = lds32(sK + ((ni * 8 + g) * QS_U + kc + 4 + t) * 4);
                MMA_F16(s[ni][0], s[ni][1], s[ni][2], s[ni][3], a0, a1, a2, a3, b0, b1);
            }
        }

        // ---- softmax on rows r0, r1 = r0+8 ----
        const int r0 = q0 + warp_m + g;
        const int r1 = r0 + 8;
        const bool diag = (kb >= 2 * (int)blockIdx.x);
        float mx0 = -1e30f, mx1 = -1e30f;
#pragma unroll
        for (int ni = 0; ni < 8; ni++) {
            const int col = kbase + ni * 8 + 2 * t;
            float v0 = s[ni][0] * scale, v1 = s[ni][1] * scale;
            float v2 = s[ni][2] * scale, v3 = s[ni][3] * scale;
            if (diag) {
                if (col > r0) v0 = -1e30f;
                if (col + 1 > r0) v1 = -1e30f;
                if (col > r1) v2 = -1e30f;
                if (col + 1 > r1) v3 = -1e30f;
            }
            s[ni][0] = v0; s[ni][1] = v1; s[ni][2] = v2; s[ni][3] = v3;
            mx0 = fmaxf(mx0, fmaxf(v0, v1));
            mx1 = fmaxf(mx1, fmaxf(v2, v3));
        }
        mx0 = fmaxf(mx0, __shfl_xor_sync(0xffffffffu, mx0, 1));
        mx0 = fmaxf(mx0, __shfl_xor_sync(0xffffffffu, mx0, 2));
        mx1 = fmaxf(mx1, __shfl_xor_sync(0xffffffffu, mx1, 1));
        mx1 = fmaxf(mx1, __shfl_xor_sync(0xffffffffu, mx1, 2));
        const float mn0 = fmaxf(m0, mx0);
        const float mn1 = fmaxf(m1, mx1);
        float rs0 = 0.0f, rs1 = 0.0f;
#pragma unroll
        for (int ni = 0; ni < 8; ni++) {
            float p0 = __expf(s[ni][0] - mn0);
            float p1 = __expf(s[ni][1] - mn0);
            float p2 = __expf(s[ni][2] - mn1);
            float p3 = __expf(s[ni][3] - mn1);
            rs0 += p0 + p1; rs1 += p2 + p3;
            Ps[(warp_m + g) * PT_U + ni * 4 + t] = pack_h2(p0, p1);
            Ps[(warp_m + g + 8) * PT_U + ni * 4 + t] = pack_h2(p2, p3);
        }
        rs0 += __shfl_xor_sync(0xffffffffu, rs0, 1);
        rs0 += __shfl_xor_sync(0xffffffffu, rs0, 2);
        rs1 += __shfl_xor_sync(0xffffffffu, rs1, 1);
        rs1 += __shfl_xor_sync(0xffffffffu, rs1, 2);
        const float al0 = __expf(m0 - mn0);
        const float al1 = __expf(m1 - mn1);
        l0 = l0 * al0 + rs0;
        l1 = l1 * al1 + rs1;
        m0 = mn0; m1 = mn1;
#pragma unroll
        for (int ni = 0; ni < 16; ni++) {
            o[ni][0] *= al0; o[ni][1] *= al0;
            o[ni][2] *= al1; o[ni][3] *= al1;
        }
        __syncwarp();

        // ---- O += P V : 4 k16 steps over 64 keys ----
#pragma unroll
        for (int ks = 0; ks < 4; ks++) {
            const int kc = ks * 8;
            uint32_t a0 = lds32(sP + ((warp_m + g) * PT_U + kc + t) * 4);
            uint32_t a1 = lds32(sP + ((warp_m + g + 8) * PT_U + kc + t) * 4);
            uint32_t a2 = lds32(sP + ((warp_m + g) * PT_U + kc + 4 + t) * 4);
            uint32_t a3 = lds32(sP + ((warp_m + g + 8) * PT_U + kc + 4 + t) * 4);
#pragma unroll
            for (int ni = 0; ni < 16; ni++) {
                uint32_t b0 = lds32(sV + ((ni * 8 + g) * PT_U + kc + t) * 4);
                uint32_t b1 = lds32(sV + ((ni * 8 + g) * PT_U + kc + 4 + t) * 4);
                MMA_F16(o[ni][0], o[ni][1], o[ni][2], o[ni][3], a0, a1, a2, a3, b0, b1);
            }
        }
        __syncwarp();
    }

    // final: normalize, round to fp16, store (feeds fp16 O-projection)
    const float inv0 = 1.0f / l0;
    const float inv1 = 1.0f / l1;
    const int r0 = q0 + warp_m + g;
#pragma unroll
    for (int ni = 0; ni < 16; ni++) {
        const int col = ni * 8 + 2 * t;
        *(__half2*)(Oh + (size_t)r0 * Dm + col) =
            __floats2half2_rn(o[ni][0] * inv0, o[ni][1] * inv0);
        *(__half2*)(Oh + (size_t)(r0 + 8) * Dm + col) =
            __floats2half2_rn(o[ni][2] * inv1, o[ni][3] * inv1);
    }
}

// ---------------------------------------------------------------------------
// Launch: round(fp16) -> fused QKV proj -> flash(rope fused) -> O proj
// ---------------------------------------------------------------------------
extern "C" void kernel_launch(void* const* d_in, const int* in_sizes, int n_in,
                              void* d_out, int out_size) {
    const float* x = (const float*)d_in[0];
    const float* fc = (const float*)d_in[1];
    const float* fs = (const float*)d_in[2];
    const float* wq = (const float*)d_in[6];
    const float* wk = (const float*)d_in[7];
    const float* wv = (const float*)d_in[8];
    const float* wo = (const float*)d_in[9];
    float* out = (float*)d_out;

    float *qp, *kp, *vp;
    __half *ah, *xh, *wqh, *wkh, *wvh, *woh;
    cudaGetSymbolAddress((void**)&qp, g_q);
    cudaGetSymbolAddress((void**)&kp, g_k);
    cudaGetSymbolAddress((void**)&vp, g_v);
    cudaGetSymbolAddress((void**)&ah, g_attn_h);
    cudaGetSymbolAddress((void**)&xh, g_xh);
    cudaGetSymbolAddress((void**)&wqh, g_wqh);
    cudaGetSymbolAddress((void**)&wkh, g_wkh);
    cudaGetSymbolAddress((void**)&wvh, g_wvh);
    cudaGetSymbolAddress((void**)&woh, g_woh);

    const int M = Bz * Sq;  // 2048

    // prep: fp16-round x and weights
    {
        int nx4 = (Bz * Sq * Dm) / 4;
        int nw4 = (Dm * Dm) / 4;
        round_fp16_kernel<<<(nx4 + 255) / 256, 256>>>((const float4*)x, (__half2*)xh, nx4);
        round_fp16_kernel<<<(nw4 + 255) / 256, 256>>>((const float4*)wq, (__half2*)wqh, nw4);
        round_fp16_kernel<<<(nw4 + 255) / 256, 256>>>((const float4*)wk, (__half2*)wkh, nw4);
        round_fp16_kernel<<<(nw4 + 255) / 256, 256>>>((const float4*)wv, (__half2*)wvh, nw4);
        round_fp16_kernel<<<(nw4 + 255) / 256, 256>>>((const float4*)wo, (__half2*)woh, nw4);
    }

    cudaFuncSetAttribute(gemm_hmma, cudaFuncAttributeMaxDynamicSharedMemorySize, GEMM_SMEM);

    // Fused QKV projection: gridDim.z selects (W, C)
    dim3 gqkv(Dm / BN, M / BM, 3);  // (16,16,3)
    gemm_hmma<<<gqkv, 256, GEMM_SMEM>>>(xh, wqh, wkh, wvh, qp, kp, vp, M, Dm, Dm);

    // Flash attention with fused RoPE
    cudaFuncSetAttribute(flash_h_kernel, cudaFuncAttributeMaxDynamicSharedMemorySize,
                         FLASH_SMEM);
    dim3 fg(Sq / FQ, Bz * Hh);  // (8, 64)
    flash_h_kernel<<<fg, 256, FLASH_SMEM>>>(qp, kp, vp, fc, fs, ah);

    // O projection (single-z grid)
    dim3 go(Dm / BN, M / BM, 1);
    gemm_hmma<<<go, 256, GEMM_SMEM>>>(ah, woh, woh, woh, out, out, out, M, Dm, Dm);
}

// round 16
// speedup vs baseline: 7.5639x; 1.0785x over previous
#include <cuda_runtime.h>
#include <cuda_fp16.h>
#include <math.h>
#include <stdint.h>

#define Bz 2
#define Sq 1024
#define Dm 4096
#define Hh 32
#define HDim 128

// Scratch (device globals: no allocation allowed in kernel_launch)
__device__ __half g_qh[Bz * Sq * Dm];
__device__ __half g_kh[Bz * Sq * Dm];
__device__ __half g_vh[Bz * Sq * Dm];
__device__ __half g_attn_h[Bz * Sq * Dm];  // flash output, fp16
__device__ __half g_xh[Bz * Sq * Dm];      // fp16-rounded x
__device__ __half g_wqh[Dm * Dm];
__device__ __half g_wkh[Dm * Dm];
__device__ __half g_wvh[Dm * Dm];
__device__ __half g_woh[Dm * Dm];

// ===========================================================================
// helpers
// ===========================================================================
__device__ __forceinline__ uint32_t smem_u32(const void* p) {
    uint32_t a;
    asm("{ .reg .u64 t; cvta.to.shared.u64 t, %1; cvt.u32.u64 %0, t; }" : "=r"(a) : "l"(p));
    return a;
}
#define CP_ASYNC_CG(dst, src) \
    asm volatile("cp.async.cg.shared.global [%0], [%1], 16;" :: "r"(dst), "l"(src))
#define CP_ASYNC_COMMIT() asm volatile("cp.async.commit_group;" ::: "memory")
#define CP_ASYNC_WAIT(n) asm volatile("cp.async.wait_group %0;" :: "n"(n) : "memory")

__device__ __forceinline__ uint32_t lds32(uint32_t addr) {
    uint32_t v;
    asm volatile("ld.shared.b32 %0, [%1];" : "=r"(v) : "r"(addr));
    return v;
}
#define MMA_F16(d0,d1,d2,d3,a0,a1,a2,a3,b0,b1) \
    asm volatile( \
        "mma.sync.aligned.m16n8k16.row.col.f32.f16.f16.f32 " \
        "{%0,%1,%2,%3}, {%4,%5,%6,%7}, {%8,%9}, {%0,%1,%2,%3};" \
        : "+f"(d0), "+f"(d1), "+f"(d2), "+f"(d3) \
        : "r"(a0), "r"(a1), "r"(a2), "r"(a3), "r"(b0), "r"(b1))

__device__ __forceinline__ uint32_t pack_h2(float a, float b) {
    __half2 h = __floats2half2_rn(a, b);
    return *(uint32_t*)&h;
}

// ===========================================================================
// Prep: fused elementwise fp16 rounding of x + 4 weights (blockIdx.z selects)
// ===========================================================================
__global__ __launch_bounds__(256) void round_all_kernel(
    const float4* __restrict__ x, const float4* __restrict__ wq,
    const float4* __restrict__ wk, const float4* __restrict__ wv,
    const float4* __restrict__ wo,
    __half2* __restrict__ xh, __half2* __restrict__ wqh,
    __half2* __restrict__ wkh, __half2* __restrict__ wvh,
    __half2* __restrict__ woh, int nx4, int nw4) {
    const int z = blockIdx.z;
    const float4* src = (z == 0) ? x : (z == 1) ? wq : (z == 2) ? wk : (z == 3) ? wv : wo;
    __half2* dst = (z == 0) ? xh : (z == 1) ? wqh : (z == 2) ? wkh : (z == 3) ? wvh : woh;
    const int n4 = (z == 0) ? nx4 : nw4;
    int i = blockIdx.x * blockDim.x + threadIdx.x;
    if (i >= n4) return;
    float4 v = src[i];
    dst[i * 2 + 0] = __floats2half2_rn(v.x, v.y);
    dst[i * 2 + 1] = __floats2half2_rn(v.z, v.w);
}

// ===========================================================================
// FP16 mma.sync GEMM, 3-stage cp.async pipeline, 2 CTAs/SM.
// C[z][M,N] = A[M,K] * W[z][N,K]^T  — blockIdx.z selects (W, C).
// CTA 128m x 128n, k-tile 64 fp16 (128B rows), 8 warps (64m x 32n), m16n8k16.
// HOUT: write __half output (QKV); else fp32 (final O-projection).
// ===========================================================================
#define BM 128
#define BN 128
#define BKH 64
#define STAGES 3
#define STAGE_BYTES ((BM + BN) * 128)         // 32768
#define GEMM_SMEM (STAGES * STAGE_BYTES)      // 98304

template <bool HOUT>
__global__ __launch_bounds__(256, 2) void gemm_hmma(const __half* __restrict__ A,
                                                    const __half* __restrict__ W0,
                                                    const __half* __restrict__ W1,
                                                    const __half* __restrict__ W2,
                                                    void* __restrict__ C0,
                                                    void* __restrict__ C1,
                                                    void* __restrict__ C2,
                                                    int M, int N, int K) {
    const __half* W = (blockIdx.z == 0) ? W0 : (blockIdx.z == 1) ? W1 : W2;
    void* C = (blockIdx.z == 0) ? C0 : (blockIdx.z == 1) ? C1 : C2;

    extern __shared__ char smem[];
    const uint32_t sbase = smem_u32(smem);
    const int tid = threadIdx.x;
    const int wid = tid >> 5;
    const int lane = tid & 31;
    const int g = lane >> 2;
    const int t = lane & 3;
    const int warp_m = (wid & 1) * 64;
    const int warp_n = (wid >> 1) * 32;
    const int bm = blockIdx.y * BM;
    const int bn = blockIdx.x * BN;
    const int niter = K / BKH;   // 64

    const int lrow = tid >> 3;
    const int lc = tid & 7;

    float acc[4][4][4];
#pragma unroll
    for (int mi = 0; mi < 4; mi++)
#pragma unroll
        for (int ni = 0; ni < 4; ni++)
#pragma unroll
            for (int r = 0; r < 4; r++) acc[mi][ni][r] = 0.0f;

    auto issue = [&](int kt, int s) {
        if (kt < niter) {
            const uint32_t sA = sbase + s * STAGE_BYTES;
            const uint32_t sB = sA + BM * 128;
            const int k0 = kt * BKH;
#pragma unroll
            for (int i = 0; i < 4; i++) {
                int row = lrow + i * 32;
                uint32_t dst = sA + row * 128 + ((lc ^ (row & 7)) << 4);
                const __half* src = A + (size_t)(bm + row) * K + k0 + lc * 8;
                CP_ASYNC_CG(dst, src);
            }
#pragma unroll
            for (int i = 0; i < 4; i++) {
                int row = lrow + i * 32;
                uint32_t dst = sB + row * 128 + ((lc ^ (row & 7)) << 4);
                const __half* src = W + (size_t)(bn + row) * K + k0 + lc * 8;
                CP_ASYNC_CG(dst, src);
            }
        }
        CP_ASYNC_COMMIT();
    };

#pragma unroll
    for (int s = 0; s < STAGES - 1; s++) issue(s, s);

    int rs = 0;
    for (int kt = 0; kt < niter; kt++) {
        CP_ASYNC_WAIT(STAGES - 2);
        __syncthreads();
        issue(kt + STAGES - 1, (rs + STAGES - 1 >= STAGES) ? rs - 1 : rs + STAGES - 1);

        const uint32_t sA = sbase + rs * STAGE_BYTES;
        const uint32_t sB = sA + BM * 128;
#pragma unroll
        for (int ks = 0; ks < 4; ks++) {
            const int c0 = (((2 * ks) ^ g) << 4) + t * 4;
            const int c1 = (((2 * ks + 1) ^ g) << 4) + t * 4;
            uint32_t af[4][4];
#pragma unroll
            for (int mi = 0; mi < 4; mi++) {
                const int r0 = warp_m + mi * 16 + g;
                af[mi][0] = lds32(sA + r0 * 128 + c0);
                af[mi][1] = lds32(sA + (r0 + 8) * 128 + c0);
                af[mi][2] = lds32(sA + r0 * 128 + c1);
                af[mi][3] = lds32(sA + (r0 + 8) * 128 + c1);
            }
#pragma unroll
            for (int ni = 0; ni < 4; ni++) {
                const int rn = warp_n + ni * 8 + g;
                uint32_t b0 = lds32(sB + rn * 128 + c0);
                uint32_t b1 = lds32(sB + rn * 128 + c1);
#pragma unroll
                for (int mi = 0; mi < 4; mi++) {
                    MMA_F16(acc[mi][ni][0], acc[mi][ni][1], acc[mi][ni][2], acc[mi][ni][3],
                            af[mi][0], af[mi][1], af[mi][2], af[mi][3], b0, b1);
                }
            }
        }
        if (++rs == STAGES) rs = 0;
    }

#pragma unroll
    for (int mi = 0; mi < 4; mi++) {
        const int row = bm + warp_m + mi * 16 + g;
#pragma unroll
        for (int ni = 0; ni < 4; ni++) {
            const int col = bn + warp_n + ni * 8 + 2 * t;
            if (HOUT) {
                __half* Ch = (__half*)C;
                *(__half2*)(Ch + (size_t)row * N + col) =
                    __floats2half2_rn(acc[mi][ni][0], acc[mi][ni][1]);
                *(__half2*)(Ch + (size_t)(row + 8) * N + col) =
                    __floats2half2_rn(acc[mi][ni][2], acc[mi][ni][3]);
            } else {
                float* Cf = (float*)C;
                *(float2*)(Cf + (size_t)row * N + col) =
                    make_float2(acc[mi][ni][0], acc[mi][ni][1]);
                *(float2*)(Cf + (size_t)(row + 8) * N + col) =
                    make_float2(acc[mi][ni][2], acc[mi][ni][3]);
            }
        }
    }
}

// ===========================================================================
// Flash attention, fp16 mma, RoPE fused into Q/K loads (fp16 inputs). Causal.
// CTA = (b,h, 128 q-rows), 8 warps (16 q-rows each), k-tile 64.
// Smem (half2 units): Qs[128][68], Ks[64][68], Vt[128][36] (V^T), Ps[128][36].
// ===========================================================================
#define FQ 128
#define FKT 64
#define QS_U 68
#define PT_U 36
#define FLASH_SMEM ((FQ * QS_U + FKT * QS_U + HDim * PT_U + FQ * PT_U) * 4)  // 89088

__global__ __launch_bounds__(256, 2) void flash_h_kernel(const __half* __restrict__ Q,
                                                         const __half* __restrict__ K,
                                                         const __half* __restrict__ V,
                                                         const float* __restrict__ fcos,
                                                         const float* __restrict__ fsin,
                                                         __half* __restrict__ O) {
    extern __shared__ char smraw[];
    uint32_t* Qs = (uint32_t*)smraw;                 // [128][68]
    uint32_t* Ks = Qs + FQ * QS_U;                   // [64][68]
    uint32_t* Vt = Ks + FKT * QS_U;                  // [128][36]  Vt[d][k-half2]
    uint32_t* Ps = Vt + HDim * PT_U;                 // [128][36]
    const uint32_t sQ = smem_u32(Qs);
    const uint32_t sK = smem_u32(Ks);
    const uint32_t sV = smem_u32(Vt);
    const uint32_t sP = smem_u32(Ps);

    const int bh = blockIdx.y;
    const int b = bh >> 5;
    const int h = bh & 31;
    const int q0 = blockIdx.x * FQ;

    const __half* Qh = Q + ((size_t)b * Sq) * Dm + h * HDim;
    const __half* Kh = K + ((size_t)b * Sq) * Dm + h * HDim;
    const __half* Vh = V + ((size_t)b * Sq) * Dm + h * HDim;
    __half* Oh = O + ((size_t)b * Sq) * Dm + h * HDim;

    const int tid = threadIdx.x;
    const int wid = tid >> 5;
    const int lane = tid & 31;
    const int g = lane >> 2;
    const int t = lane & 3;
    const int warp_m = wid * 16;
    const float scale = 0.08838834764831844f;  // 1/sqrt(128)

    // Load Q tile once, applying RoPE. 16B chunk = 8 dims = 4 pairs.
    for (int idx = tid; idx < FQ * 16; idx += 256) {
        int row = idx >> 4;
        int ch = idx & 15;
        int s = q0 + row;
        uint4 v = *(const uint4*)(Qh + (size_t)s * Dm + ch * 8);
        __half2* hp = (__half2*)&v;
        int p = ch * 4;
#pragma unroll
        for (int j = 0; j < 4; j++) {
            float2 f = __half22float2(hp[j]);
            float c = fcos[s * 64 + p + j], sn = fsin[s * 64 + p + j];
            Qs[row * QS_U + p + j] = pack_h2(f.x * c - f.y * sn, f.x * sn + f.y * c);
        }
    }

    float m0 = -1e30f, m1 = -1e30f, l0 = 0.0f, l1 = 0.0f;
    float o[16][4];
#pragma unroll
    for (int ni = 0; ni < 16; ni++)
#pragma unroll
        for (int r = 0; r < 4; r++) o[ni][r] = 0.0f;

    const int nkt = 2 * blockIdx.x + 2;
    for (int kb = 0; kb < nkt; kb++) {
        const int kbase = kb * FKT;
        __syncthreads();
        // K tile with RoPE
        for (int idx = tid; idx < FKT * 16; idx += 256) {
            int row = idx >> 4;
            int ch = idx & 15;
            int s = kbase + row;
            uint4 v = *(const uint4*)(Kh + (size_t)s * Dm + ch * 8);
            __half2* hp = (__half2*)&v;
            int p = ch * 4;
#pragma unroll
            for (int j = 0; j < 4; j++) {
                float2 f = __half22float2(hp[j]);
                float c = fcos[s * 64 + p + j], sn = fsin[s * 64 + p + j];
                Ks[row * QS_U + p + j] = pack_h2(f.x * c - f.y * sn, f.x * sn + f.y * c);
            }
        }
        // V tile transposed: Vt[d][kj2] = (V[2kj2][d], V[2kj2+1][d]).
        // kj2 fastest within warp -> conflict-free STS.
        for (int idx = tid; idx < 512; idx += 256) {
            int kj2 = idx & 31;
            int ch = idx >> 5;
            const __half* r0p = Vh + (size_t)(kbase + 2 * kj2) * Dm + ch * 8;
            uint4 a = *(const uint4*)r0p;
            uint4 bb = *(const uint4*)(r0p + Dm);
            __half* ha = (__half*)&a;
            __half* hb = (__half*)&bb;
#pragma unroll
            for (int j = 0; j < 8; j++) {
                __half2 hv = __halves2half2(ha[j], hb[j]);
                Vt[(ch * 8 + j) * PT_U + kj2] = *(uint32_t*)&hv;
            }
        }
        __syncthreads();

        // ---- S = Q K^T : 8 k16 steps over 128 dims ----
        float s[8][4];
#pragma unroll
        for (int ni = 0; ni < 8; ni++)
#pragma unroll
            for (int r = 0; r < 4; r++) s[ni][r] = 0.0f;

#pragma unroll
        for (int ks = 0; ks < 8; ks++) {
            const int kc = ks * 8;   // half2 col base
            uint32_t a0 = lds32(sQ + ((warp_m + g) * QS_U + kc + t) * 4);
            uint32_t a1 = lds32(sQ + ((warp_m + g + 8) * QS_U + kc + t) * 4);
            uint32_t a2 = lds32(sQ + ((warp_m + g) * QS_U + kc + 4 + t) * 4);
            uint32_t a3 = lds32(sQ + ((warp_m + g + 8) * QS_U + kc + 4 + t) * 4);
#pragma unroll
            for (int ni = 0; ni < 8; ni++) {
                uint32_t b0 = lds32(sK + ((ni * 8 + g) * QS_U + kc + t) * 4);
                uint32_t b1 = lds32(sK + ((ni * 8 + g) * QS_U + kc + 4 + t) * 4);
                MMA_F16(s[ni][0], s[ni][1], s[ni][2], s[ni][3], a0, a1, a2, a3, b0, b1);
            }
        }

        // ---- softmax on rows r0, r1 = r0+8 ----
        const int r0 = q0 + warp_m + g;
        const int r1 = r0 + 8;
        const bool diag = (kb >= 2 * (int)blockIdx.x);
        float mx0 = -1e30f, mx1 = -1e30f;
#pragma unroll
        for (int ni = 0; ni < 8; ni++) {
            const int col = kbase + ni * 8 + 2 * t;
            float v0 = s[ni][0] * scale, v1 = s[ni][1] * scale;
            float v2 = s[ni][2] * scale, v3 = s[ni][3] * scale;
            if (diag) {
                if (col > r0) v0 = -1e30f;
                if (col + 1 > r0) v1 = -1e30f;
                if (col > r1) v2 = -1e30f;
                if (col + 1 > r1) v3 = -1e30f;
            }
            s[ni][0] = v0; s[ni][1] = v1; s[ni][2] = v2; s[ni][3] = v3;
            mx0 = fmaxf(mx0, fmaxf(v0, v1));
            mx1 = fmaxf(mx1, fmaxf(v2, v3));
        }
        mx0 = fmaxf(mx0, __shfl_xor_sync(0xffffffffu, mx0, 1));
        mx0 = fmaxf(mx0, __shfl_xor_sync(0xffffffffu, mx0, 2));
        mx1 = fmaxf(mx1, __shfl_xor_sync(0xffffffffu, mx1, 1));
        mx1 = fmaxf(mx1, __shfl_xor_sync(0xffffffffu, mx1, 2));
        const float mn0 = fmaxf(m0, mx0);
        const float mn1 = fmaxf(m1, mx1);
        float rs0 = 0.0f, rs1 = 0.0f;
#pragma unroll
        for (int ni = 0; ni < 8; ni++) {
            float p0 = __expf(s[ni][0] - mn0);
            float p1 = __expf(s[ni][1] - mn0);
            float p2 = __expf(s[ni][2] - mn1);
            float p3 = __expf(s[ni][3] - mn1);
            rs0 += p0 + p1; rs1 += p2 + p3;
            Ps[(warp_m + g) * PT_U + ni * 4 + t] = pack_h2(p0, p1);
            Ps[(warp_m + g + 8) * PT_U + ni * 4 + t] = pack_h2(p2, p3);
        }
        rs0 += __shfl_xor_sync(0xffffffffu, rs0, 1);
        rs0 += __shfl_xor_sync(0xffffffffu, rs0, 2);
        rs1 += __shfl_xor_sync(0xffffffffu, rs1, 1);
        rs1 += __shfl_xor_sync(0xffffffffu, rs1, 2);
        const float al0 = __expf(m0 - mn0);
        const float al1 = __expf(m1 - mn1);
        l0 = l0 * al0 + rs0;
        l1 = l1 * al1 + rs1;
        m0 = mn0; m1 = mn1;
#pragma unroll
        for (int ni = 0; ni < 16; ni++) {
            o[ni][0] *= al0; o[ni][1] *= al0;
            o[ni][2] *= al1; o[ni][3] *= al1;
        }
        __syncwarp();

        // ---- O += P V : 4 k16 steps over 64 keys ----
#pragma unroll
        for (int ks = 0; ks < 4; ks++) {
            const int kc = ks * 8;
            uint32_t a0 = lds32(sP + ((warp_m + g) * PT_U + kc + t) * 4);
            uint32_t a1 = lds32(sP + ((warp_m + g + 8) * PT_U + kc + t) * 4);
            uint32_t a2 = lds32(sP + ((warp_m + g) * PT_U + kc + 4 + t) * 4);
            uint32_t a3 = lds32(sP + ((warp_m + g + 8) * PT_U + kc + 4 + t) * 4);
#pragma unroll
            for (int ni = 0; ni < 16; ni++) {
                uint32_t b0 = lds32(sV + ((ni * 8 + g) * PT_U + kc + t) * 4);
                uint32_t b1 = lds32(sV + ((ni * 8 + g) * PT_U + kc + 4 + t) * 4);
                MMA_F16(o[ni][0], o[ni][1], o[ni][2], o[ni][3], a0, a1, a2, a3, b0, b1);
            }
        }
        __syncwarp();
    }

    // final: normalize, round to fp16, store (feeds fp16 O-projection)
    const float inv0 = 1.0f / l0;
    const float inv1 = 1.0f / l1;
    const int r0 = q0 + warp_m + g;
#pragma unroll
    for (int ni = 0; ni < 16; ni++) {
        const int col = ni * 8 + 2 * t;
        *(__half2*)(Oh + (size_t)r0 * Dm + col) =
            __floats2half2_rn(o[ni][0] * inv0, o[ni][1] * inv0);
        *(__half2*)(Oh + (size_t)(r0 + 8) * Dm + col) =
            __floats2half2_rn(o[ni][2] * inv1, o[ni][3] * inv1);
    }
}

// ---------------------------------------------------------------------------
// Launch: fused round -> fused QKV proj (fp16 out) -> flash -> O proj (fp32)
// ---------------------------------------------------------------------------
extern "C" void kernel_launch(void* const* d_in, const int* in_sizes, int n_in,
                              void* d_out, int out_size) {
    const float* x = (const float*)d_in[0];
    const float* fc = (const float*)d_in[1];
    const float* fs = (const float*)d_in[2];
    const float* wq = (const float*)d_in[6];
    const float* wk = (const float*)d_in[7];
    const float* wv = (const float*)d_in[8];
    const float* wo = (const float*)d_in[9];
    float* out = (float*)d_out;

    __half *qh, *kh, *vh, *ah, *xh, *wqh, *wkh, *wvh, *woh;
    cudaGetSymbolAddress((void**)&qh, g_qh);
    cudaGetSymbolAddress((void**)&kh, g_kh);
    cudaGetSymbolAddress((void**)&vh, g_vh);
    cudaGetSymbolAddress((void**)&ah, g_attn_h);
    cudaGetSymbolAddress((void**)&xh, g_xh);
    cudaGetSymbolAddress((void**)&wqh, g_wqh);
    cudaGetSymbolAddress((void**)&wkh, g_wkh);
    cudaGetSymbolAddress((void**)&wvh, g_wvh);
    cudaGetSymbolAddress((void**)&woh, g_woh);

    const int M = Bz * Sq;  // 2048
    const int nx4 = (Bz * Sq * Dm) / 4;  // 2097152
    const int nw4 = (Dm * Dm) / 4;       // 4194304

    // fused prep: one launch rounds x + all 4 weights
    {
        dim3 gr((nw4 + 255) / 256, 1, 5);
        round_all_kernel<<<gr, 256>>>((const float4*)x, (const float4*)wq,
                                      (const float4*)wk, (const float4*)wv,
                                      (const float4*)wo, (__half2*)xh, (__half2*)wqh,
                                      (__half2*)wkh, (__half2*)wvh, (__half2*)woh,
                                      nx4, nw4);
    }

    cudaFuncSetAttribute(gemm_hmma<true>, cudaFuncAttributeMaxDynamicSharedMemorySize,
                         GEMM_SMEM);
    cudaFuncSetAttribute(gemm_hmma<false>, cudaFuncAttributeMaxDynamicSharedMemorySize,
                         GEMM_SMEM);

    // Fused QKV projection (fp16 outputs): gridDim.z selects (W, C)
    dim3 gqkv(Dm / BN, M / BM, 3);  // (32,16,3)
    gemm_hmma<true><<<gqkv, 256, GEMM_SMEM>>>(xh, wqh, wkh, wvh, qh, kh, vh, M, Dm, Dm);

    // Flash attention with fused RoPE (fp16 in/out)
    cudaFuncSetAttribute(flash_h_kernel, cudaFuncAttributeMaxDynamicSharedMemorySize,
                         FLASH_SMEM);
    dim3 fg(Sq / FQ, Bz * Hh);  // (8, 64)
    flash_h_kernel<<<fg, 256, FLASH_SMEM>>>(qh, kh, vh, fc, fs, ah);

    // O projection (fp32 output)
    dim3 go(Dm / BN, M / BM, 1);  // (32,16,1)
    gemm_hmma<false><<<go, 256, GEMM_SMEM>>>(ah, woh, woh, woh, out, out, out, M, Dm, Dm);
}

// round 17
// speedup vs baseline: 8.2711x; 1.0935x over previous
#include <cuda_runtime.h>
#include <cuda_fp16.h>
#include <math.h>
#include <stdint.h>

#define Bz 2
#define Sq 1024
#define Dm 4096
#define Hh 32
#define HDim 128

// Scratch (device globals: no allocation allowed in kernel_launch)
__device__ __half g_qh[Bz * Sq * Dm];
__device__ __half g_kh[Bz * Sq * Dm];
__device__ __half g_vh[Bz * Sq * Dm];
__device__ __half g_attn_h[Bz * Sq * Dm];  // flash output, fp16
__device__ __half g_xh[Bz * Sq * Dm];      // fp16-rounded x
__device__ __half g_wqh[Dm * Dm];
__device__ __half g_wkh[Dm * Dm];
__device__ __half g_wvh[Dm * Dm];
__device__ __half g_woh[Dm * Dm];

// ===========================================================================
// helpers
// ===========================================================================
__device__ __forceinline__ uint32_t smem_u32(const void* p) {
    uint32_t a;
    asm("{ .reg .u64 t; cvta.to.shared.u64 t, %1; cvt.u32.u64 %0, t; }" : "=r"(a) : "l"(p));
    return a;
}
#define CP_ASYNC_CG(dst, src) \
    asm volatile("cp.async.cg.shared.global [%0], [%1], 16;" :: "r"(dst), "l"(src))
#define CP_ASYNC_COMMIT() asm volatile("cp.async.commit_group;" ::: "memory")
#define CP_ASYNC_WAIT(n) asm volatile("cp.async.wait_group %0;" :: "n"(n) : "memory")

__device__ __forceinline__ uint32_t lds32(uint32_t addr) {
    uint32_t v;
    asm volatile("ld.shared.b32 %0, [%1];" : "=r"(v) : "r"(addr));
    return v;
}
#define LDSM_X4(r0, r1, r2, r3, addr) \
    asm volatile("ldmatrix.sync.aligned.m8n8.x4.shared.b16 {%0,%1,%2,%3}, [%4];" \
                 : "=r"(r0), "=r"(r1), "=r"(r2), "=r"(r3) : "r"(addr))
#define LDSM_X2(r0, r1, addr) \
    asm volatile("ldmatrix.sync.aligned.m8n8.x2.shared.b16 {%0,%1}, [%2];" \
                 : "=r"(r0), "=r"(r1) : "r"(addr))
#define MMA_F16(d0,d1,d2,d3,a0,a1,a2,a3,b0,b1) \
    asm volatile( \
        "mma.sync.aligned.m16n8k16.row.col.f32.f16.f16.f32 " \
        "{%0,%1,%2,%3}, {%4,%5,%6,%7}, {%8,%9}, {%0,%1,%2,%3};" \
        : "+f"(d0), "+f"(d1), "+f"(d2), "+f"(d3) \
        : "r"(a0), "r"(a1), "r"(a2), "r"(a3), "r"(b0), "r"(b1))

__device__ __forceinline__ uint32_t pack_h2(float a, float b) {
    __half2 h = __floats2half2_rn(a, b);
    return *(uint32_t*)&h;
}

// ===========================================================================
// Prep: fused elementwise fp16 rounding of x + 4 weights (blockIdx.z selects)
// ===========================================================================
__global__ __launch_bounds__(256) void round_all_kernel(
    const float4* __restrict__ x, const float4* __restrict__ wq,
    const float4* __restrict__ wk, const float4* __restrict__ wv,
    const float4* __restrict__ wo,
    __half2* __restrict__ xh, __half2* __restrict__ wqh,
    __half2* __restrict__ wkh, __half2* __restrict__ wvh,
    __half2* __restrict__ woh, int nx4, int nw4) {
    const int z = blockIdx.z;
    const float4* src = (z == 0) ? x : (z == 1) ? wq : (z == 2) ? wk : (z == 3) ? wv : wo;
    __half2* dst = (z == 0) ? xh : (z == 1) ? wqh : (z == 2) ? wkh : (z == 3) ? wvh : woh;
    const int n4 = (z == 0) ? nx4 : nw4;
    int i = blockIdx.x * blockDim.x + threadIdx.x;
    if (i >= n4) return;
    float4 v = src[i];
    dst[i * 2 + 0] = __floats2half2_rn(v.x, v.y);
    dst[i * 2 + 1] = __floats2half2_rn(v.z, v.w);
}

// ===========================================================================
// FP16 mma.sync GEMM, 3-stage cp.async pipeline, 2 CTAs/SM, ldmatrix feeds.
// C[z][M,N] = A[M,K] * W[z][N,K]^T  — blockIdx.z selects (W, C).
// CTA 128m x 128n, k-tile 64 fp16 (128B rows), 8 warps (64m x 32n), m16n8k16.
// ===========================================================================
#define BM 128
#define BN 128
#define BKH 64
#define STAGES 3
#define STAGE_BYTES ((BM + BN) * 128)         // 32768
#define GEMM_SMEM (STAGES * STAGE_BYTES)      // 98304

template <bool HOUT>
__global__ __launch_bounds__(256, 2) void gemm_hmma(const __half* __restrict__ A,
                                                    const __half* __restrict__ W0,
                                                    const __half* __restrict__ W1,
                                                    const __half* __restrict__ W2,
                                                    void* __restrict__ C0,
                                                    void* __restrict__ C1,
                                                    void* __restrict__ C2,
                                                    int M, int N, int K) {
    const __half* W = (blockIdx.z == 0) ? W0 : (blockIdx.z == 1) ? W1 : W2;
    void* C = (blockIdx.z == 0) ? C0 : (blockIdx.z == 1) ? C1 : C2;

    extern __shared__ char smem[];
    const uint32_t sbase = smem_u32(smem);
    const int tid = threadIdx.x;
    const int wid = tid >> 5;
    const int lane = tid & 31;
    const int g = lane >> 2;
    const int t = lane & 3;
    const int warp_m = (wid & 1) * 64;
    const int warp_n = (wid >> 1) * 32;
    const int bm = blockIdx.y * BM;
    const int bn = blockIdx.x * BN;
    const int niter = K / BKH;   // 64

    const int lrow = tid >> 3;
    const int lc = tid & 7;

    // ldmatrix per-lane row addressing
    const int j = lane & 7;        // supplying row within 8-row matrix
    const int qsel = lane >> 3;    // which matrix this lane feeds (x4)
    const int qlo = qsel & 1;      // +8 rows
    const int qhi = qsel >> 1;     // +1 k-chunk
    const int bhalf = qsel & 1;    // x2: matrix 0/1 -> k-chunk

    float acc[4][4][4];
#pragma unroll
    for (int mi = 0; mi < 4; mi++)
#pragma unroll
        for (int ni = 0; ni < 4; ni++)
#pragma unroll
            for (int r = 0; r < 4; r++) acc[mi][ni][r] = 0.0f;

    auto issue = [&](int kt, int s) {
        if (kt < niter) {
            const uint32_t sA = sbase + s * STAGE_BYTES;
            const uint32_t sB = sA + BM * 128;
            const int k0 = kt * BKH;
#pragma unroll
            for (int i = 0; i < 4; i++) {
                int row = lrow + i * 32;
                uint32_t dst = sA + row * 128 + ((lc ^ (row & 7)) << 4);
                const __half* src = A + (size_t)(bm + row) * K + k0 + lc * 8;
                CP_ASYNC_CG(dst, src);
            }
#pragma unroll
            for (int i = 0; i < 4; i++) {
                int row = lrow + i * 32;
                uint32_t dst = sB + row * 128 + ((lc ^ (row & 7)) << 4);
                const __half* src = W + (size_t)(bn + row) * K + k0 + lc * 8;
                CP_ASYNC_CG(dst, src);
            }
        }
        CP_ASYNC_COMMIT();
    };

#pragma unroll
    for (int s = 0; s < STAGES - 1; s++) issue(s, s);

    int rs = 0;
    for (int kt = 0; kt < niter; kt++) {
        CP_ASYNC_WAIT(STAGES - 2);
        __syncthreads();
        issue(kt + STAGES - 1, (rs + STAGES - 1 >= STAGES) ? rs - 1 : rs + STAGES - 1);

        const uint32_t sA = sbase + rs * STAGE_BYTES;
        const uint32_t sB = sA + BM * 128;
        // per-lane row bases (swizzle term added per ks)
        const uint32_t aRow = sA + (warp_m + qlo * 8 + j) * 128;
        const uint32_t bRow = sB + (warp_n + j) * 128;
#pragma unroll
        for (int ks = 0; ks < 4; ks++) {
            const uint32_t swzA = (uint32_t)(((2 * ks + qhi) ^ j) << 4);
            const uint32_t swzB = (uint32_t)(((2 * ks + bhalf) ^ j) << 4);
            uint32_t af[4][4];
#pragma unroll
            for (int mi = 0; mi < 4; mi++) {
                LDSM_X4(af[mi][0], af[mi][1], af[mi][2], af[mi][3],
                        aRow + mi * 16 * 128 + swzA);
            }
#pragma unroll
            for (int ni = 0; ni < 4; ni++) {
                uint32_t b0, b1;
                LDSM_X2(b0, b1, bRow + ni * 8 * 128 + swzB);
#pragma unroll
                for (int mi = 0; mi < 4; mi++) {
                    MMA_F16(acc[mi][ni][0], acc[mi][ni][1], acc[mi][ni][2], acc[mi][ni][3],
                            af[mi][0], af[mi][1], af[mi][2], af[mi][3], b0, b1);
                }
            }
        }
        if (++rs == STAGES) rs = 0;
    }

#pragma unroll
    for (int mi = 0; mi < 4; mi++) {
        const int row = bm + warp_m + mi * 16 + g;
#pragma unroll
        for (int ni = 0; ni < 4; ni++) {
            const int col = bn + warp_n + ni * 8 + 2 * t;
            if (HOUT) {
                __half* Ch = (__half*)C;
                *(__half2*)(Ch + (size_t)row * N + col) =
                    __floats2half2_rn(acc[mi][ni][0], acc[mi][ni][1]);
                *(__half2*)(Ch + (size_t)(row + 8) * N + col) =
                    __floats2half2_rn(acc[mi][ni][2], acc[mi][ni][3]);
            } else {
                float* Cf = (float*)C;
                *(float2*)(Cf + (size_t)row * N + col) =
                    make_float2(acc[mi][ni][0], acc[mi][ni][1]);
                *(float2*)(Cf + (size_t)(row + 8) * N + col) =
                    make_float2(acc[mi][ni][2], acc[mi][ni][3]);
            }
        }
    }
}

// ===========================================================================
// Flash attention, fp16 mma, RoPE fused into Q/K loads (fp16 inputs). Causal.
// (unchanged from R16)
// ===========================================================================
#define FQ 128
#define FKT 64
#define QS_U 68
#define PT_U 36
#define FLASH_SMEM ((FQ * QS_U + FKT * QS_U + HDim * PT_U + FQ * PT_U) * 4)  // 89088

__global__ __launch_bounds__(256, 2) void flash_h_kernel(const __half* __restrict__ Q,
                                                         const __half* __restrict__ K,
                                                         const __half* __restrict__ V,
                                                         const float* __restrict__ fcos,
                                                         const float* __restrict__ fsin,
                                                         __half* __restrict__ O) {
    extern __shared__ char smraw[];
    uint32_t* Qs = (uint32_t*)smraw;                 // [128][68]
    uint32_t* Ks = Qs + FQ * QS_U;                   // [64][68]
    uint32_t* Vt = Ks + FKT * QS_U;                  // [128][36]  Vt[d][k-half2]
    uint32_t* Ps = Vt + HDim * PT_U;                 // [128][36]
    const uint32_t sQ = smem_u32(Qs);
    const uint32_t sK = smem_u32(Ks);
    const uint32_t sV = smem_u32(Vt);
    const uint32_t sP = smem_u32(Ps);

    const int bh = blockIdx.y;
    const int b = bh >> 5;
    const int h = bh & 31;
    const int q0 = blockIdx.x * FQ;

    const __half* Qh = Q + ((size_t)b * Sq) * Dm + h * HDim;
    const __half* Kh = K + ((size_t)b * Sq) * Dm + h * HDim;
    const __half* Vh = V + ((size_t)b * Sq) * Dm + h * HDim;
    __half* Oh = O + ((size_t)b * Sq) * Dm + h * HDim;

    const int tid = threadIdx.x;
    const int wid = tid >> 5;
    const int lane = tid & 31;
    const int g = lane >> 2;
    const int t = lane & 3;
    const int warp_m = wid * 16;
    const float scale = 0.08838834764831844f;  // 1/sqrt(128)

    for (int idx = tid; idx < FQ * 16; idx += 256) {
        int row = idx >> 4;
        int ch = idx & 15;
        int s = q0 + row;
        uint4 v = *(const uint4*)(Qh + (size_t)s * Dm + ch * 8);
        __half2* hp = (__half2*)&v;
        int p = ch * 4;
#pragma unroll
        for (int jj = 0; jj < 4; jj++) {
            float2 f = __half22float2(hp[jj]);
            float c = fcos[s * 64 + p + jj], sn = fsin[s * 64 + p + jj];
            Qs[row * QS_U + p + jj] = pack_h2(f.x * c - f.y * sn, f.x * sn + f.y * c);
        }
    }

    float m0 = -1e30f, m1 = -1e30f, l0 = 0.0f, l1 = 0.0f;
    float o[16][4];
#pragma unroll
    for (int ni = 0; ni < 16; ni++)
#pragma unroll
        for (int r = 0; r < 4; r++) o[ni][r] = 0.0f;

    const int nkt = 2 * blockIdx.x + 2;
    for (int kb = 0; kb < nkt; kb++) {
        const int kbase = kb * FKT;
        __syncthreads();
        for (int idx = tid; idx < FKT * 16; idx += 256) {
            int row = idx >> 4;
            int ch = idx & 15;
            int s = kbase + row;
            uint4 v = *(const uint4*)(Kh + (size_t)s * Dm + ch * 8);
            __half2* hp = (__half2*)&v;
            int p = ch * 4;
#pragma unroll
            for (int jj = 0; jj < 4; jj++) {
                float2 f = __half22float2(hp[jj]);
                float c = fcos[s * 64 + p + jj], sn = fsin[s * 64 + p + jj];
                Ks[row * QS_U + p + jj] = pack_h2(f.x * c - f.y * sn, f.x * sn + f.y * c);
            }
        }
        for (int idx = tid; idx < 512; idx += 256) {
            int kj2 = idx & 31;
            int ch = idx >> 5;
            const __half* r0p = Vh + (size_t)(kbase + 2 * kj2) * Dm + ch * 8;
            uint4 a = *(const uint4*)r0p;
            uint4 bb = *(const uint4*)(r0p + Dm);
            __half* ha = (__half*)&a;
            __half* hb = (__half*)&bb;
#pragma unroll
            for (int jj = 0; jj < 8; jj++) {
                __half2 hv = __halves2half2(ha[jj], hb[jj]);
                Vt[(ch * 8 + jj) * PT_U + kj2] = *(uint32_t*)&hv;
            }
        }
        __syncthreads();

        float s[8][4];
#pragma unroll
        for (int ni = 0; ni < 8; ni++)
#pragma unroll
            for (int r = 0; r < 4; r++) s[ni][r] = 0.0f;

#pragma unroll
        for (int ks = 0; ks < 8; ks++) {
            const int kc = ks * 8;
            uint32_t a0 = lds32(sQ + ((warp_m + g) * QS_U + kc + t) * 4);
            uint32_t a1 = lds32(sQ + ((warp_m + g + 8) * QS_U + kc + t) * 4);
            uint32_t a2 = lds32(sQ + ((warp_m + g) * QS_U + kc + 4 + t) * 4);
            uint32_t a3 = lds32(sQ + ((warp_m + g + 8) * QS_U + kc + 4 + t) * 4);
#pragma unroll
            for (int ni = 0; ni < 8; ni++) {
                uint32_t b0 = lds32(sK + ((ni * 8 + g) * QS_U + kc + t) * 4);
                uint32_t b1 = lds32(sK + ((ni * 8 + g) * QS_U + kc + 4 + t) * 4);
                MMA_F16(s[ni][0], s[ni][1], s[ni][2], s[ni][3], a0, a1, a2, a3, b0, b1);
            }
        }

        const int r0 = q0 + warp_m + g;
        const int r1 = r0 + 8;
        const bool diag = (kb >= 2 * (int)blockIdx.x);
        float mx0 = -1e30f, mx1 = -1e30f;
#pragma unroll
        for (int ni = 0; ni < 8; ni++) {
            const int col = kbase + ni * 8 + 2 * t;
            float v0 = s[ni][0] * scale, v1 = s[ni][1] * scale;
            float v2 = s[ni][2] * scale, v3 = s[ni][3] * scale;
            if (diag) {
                if (col > r0) v0 = -1e30f;
                if (col + 1 > r0) v1 = -1e30f;
                if (col > r1) v2 = -1e30f;
                if (col + 1 > r1) v3 = -1e30f;
            }
            s[ni][0] = v0; s[ni][1] = v1; s[ni][2] = v2; s[ni][3] = v3;
            mx0 = fmaxf(mx0, fmaxf(v0, v1));
            mx1 = fmaxf(mx1, fmaxf(v2, v3));
        }
        mx0 = fmaxf(mx0, __shfl_xor_sync(0xffffffffu, mx0, 1));
        mx0 = fmaxf(mx0, __shfl_xor_sync(0xffffffffu, mx0, 2));
        mx1 = fmaxf(mx1, __shfl_xor_sync(0xffffffffu, mx1, 1));
        mx1 = fmaxf(mx1, __shfl_xor_sync(0xffffffffu, mx1, 2));
        const float mn0 = fmaxf(m0, mx0);
        const float mn1 = fmaxf(m1, mx1);
        float rs0 = 0.0f, rs1 = 0.0f;
#pragma unroll
        for (int ni = 0; ni < 8; ni++) {
            float p0 = __expf(s[ni][0] - mn0);
            float p1 = __expf(s[ni][1] - mn0);
            float p2 = __expf(s[ni][2] - mn1);
            float p3 = __expf(s[ni][3] - mn1);
            rs0 += p0 + p1; rs1 += p2 + p3;
            Ps[(warp_m + g) * PT_U + ni * 4 + t] = pack_h2(p0, p1);
            Ps[(warp_m + g + 8) * PT_U + ni * 4 + t] = pack_h2(p2, p3);
        }
        rs0 += __shfl_xor_sync(0xffffffffu, rs0, 1);
        rs0 += __shfl_xor_sync(0xffffffffu, rs0, 2);
        rs1 += __shfl_xor_sync(0xffffffffu, rs1, 1);
        rs1 += __shfl_xor_sync(0xffffffffu, rs1, 2);
        const float al0 = __expf(m0 - mn0);
        const float al1 = __expf(m1 - mn1);
        l0 = l0 * al0 + rs0;
        l1 = l1 * al1 + rs1;
        m0 = mn0; m1 = mn1;
#pragma unroll
        for (int ni = 0; ni < 16; ni++) {
            o[ni][0] *= al0; o[ni][1] *= al0;
            o[ni][2] *= al1; o[ni][3] *= al1;
        }
        __syncwarp();

#pragma unroll
        for (int ks = 0; ks < 4; ks++) {
            const int kc = ks * 8;
            uint32_t a0 = lds32(sP + ((warp_m + g) * PT_U + kc + t) * 4);
            uint32_t a1 = lds32(sP + ((warp_m + g + 8) * PT_U + kc + t) * 4);
            uint32_t a2 = lds32(sP + ((warp_m + g) * PT_U + kc + 4 + t) * 4);
            uint32_t a3 = lds32(sP + ((warp_m + g + 8) * PT_U + kc + 4 + t) * 4);
#pragma unroll
            for (int ni = 0; ni < 16; ni++) {
                uint32_t b0 = lds32(sV + ((ni * 8 + g) * PT_U + kc + t) * 4);
                uint32_t b1 = lds32(sV + ((ni * 8 + g) * PT_U + kc + 4 + t) * 4);
                MMA_F16(o[ni][0], o[ni][1], o[ni][2], o[ni][3], a0, a1, a2, a3, b0, b1);
            }
        }
        __syncwarp();
    }

    const float inv0 = 1.0f / l0;
    const float inv1 = 1.0f / l1;
    const int r0 = q0 + warp_m + g;
#pragma unroll
    for (int ni = 0; ni < 16; ni++) {
        const int col = ni * 8 + 2 * t;
        *(__half2*)(Oh + (size_t)r0 * Dm + col) =
            __floats2half2_rn(o[ni][0] * inv0, o[ni][1] * inv0);
        *(__half2*)(Oh + (size_t)(r0 + 8) * Dm + col) =
            __floats2half2_rn(o[ni][2] * inv1, o[ni][3] * inv1);
    }
}

// ---------------------------------------------------------------------------
// Launch: fused round -> fused QKV proj (fp16 out) -> flash -> O proj (fp32)
// ---------------------------------------------------------------------------
extern "C" void kernel_launch(void* const* d_in, const int* in_sizes, int n_in,
                              void* d_out, int out_size) {
    const float* x = (const float*)d_in[0];
    const float* fc = (const float*)d_in[1];
    const float* fs = (const float*)d_in[2];
    const float* wq = (const float*)d_in[6];
    const float* wk = (const float*)d_in[7];
    const float* wv = (const float*)d_in[8];
    const float* wo = (const float*)d_in[9];
    float* out = (float*)d_out;

    __half *qh, *kh, *vh, *ah, *xh, *wqh, *wkh, *wvh, *woh;
    cudaGetSymbolAddress((void**)&qh, g_qh);
    cudaGetSymbolAddress((void**)&kh, g_kh);
    cudaGetSymbolAddress((void**)&vh, g_vh);
    cudaGetSymbolAddress((void**)&ah, g_attn_h);
    cudaGetSymbolAddress((void**)&xh, g_xh);
    cudaGetSymbolAddress((void**)&wqh, g_wqh);
    cudaGetSymbolAddress((void**)&wkh, g_wkh);
    cudaGetSymbolAddress((void**)&wvh, g_wvh);
    cudaGetSymbolAddress((void**)&woh, g_woh);

    const int M = Bz * Sq;  // 2048
    const int nx4 = (Bz * Sq * Dm) / 4;  // 2097152
    const int nw4 = (Dm * Dm) / 4;       // 4194304

    {
        dim3 gr((nw4 + 255) / 256, 1, 5);
        round_all_kernel<<<gr, 256>>>((const float4*)x, (const float4*)wq,
                                      (const float4*)wk, (const float4*)wv,
                                      (const float4*)wo, (__half2*)xh, (__half2*)wqh,
                                      (__half2*)wkh, (__half2*)wvh, (__half2*)woh,
                                      nx4, nw4);
    }

    cudaFuncSetAttribute(gemm_hmma<true>, cudaFuncAttributeMaxDynamicSharedMemorySize,
                         GEMM_SMEM);
    cudaFuncSetAttribute(gemm_hmma<false>, cudaFuncAttributeMaxDynamicSharedMemorySize,
                         GEMM_SMEM);

    dim3 gqkv(Dm / BN, M / BM, 3);  // (32,16,3)
    gemm_hmma<true><<<gqkv, 256, GEMM_SMEM>>>(xh, wqh, wkh, wvh, qh, kh, vh, M, Dm, Dm);

    cudaFuncSetAttribute(flash_h_kernel, cudaFuncAttributeMaxDynamicSharedMemorySize,
                         FLASH_SMEM);
    dim3 fg(Sq / FQ, Bz * Hh);  // (8, 64)
    flash_h_kernel<<<fg, 256, FLASH_SMEM>>>(qh, kh, vh, fc, fs, ah);

    dim3 go(Dm / BN, M / BM, 1);  // (32,16,1)
    gemm_hmma<false><<<go, 256, GEMM_SMEM>>>(ah, woh, woh, woh, out, out, out, M, Dm, Dm);
}